// round 4
// baseline (speedup 1.0000x reference)
#include <cuda_runtime.h>

typedef unsigned long long u64;

#define B_SZ   16
#define N_SEQ  2048
#define F_DIM  256
#define BNR    (B_SZ * N_SEQ)   // 32768 rows

// ---------------- device scratch (no runtime allocation allowed) ----------------
__device__ float g_h[(size_t)BNR * F_DIM];                 // 33.5 MB
__device__ float g_q[(size_t)BNR * F_DIM];                 // also reused as R temp
__device__ float g_k[(size_t)BNR * F_DIM];
__device__ float g_v[(size_t)BNR * F_DIM];
__device__ float g_s[(size_t)B_SZ * N_SEQ * N_SEQ];        // 268 MB scores

// ---------------- packed f32x2 helpers (Blackwell 2xFP32 path) ----------------
__device__ __forceinline__ u64 dupf(float x) {
    u64 r; unsigned xi = __float_as_uint(x);
    asm("mov.b64 %0, {%1,%1};" : "=l"(r) : "r"(xi));
    return r;
}
__device__ __forceinline__ void ffma2(u64& d, u64 a, u64 b) {
    asm("fma.rn.f32x2 %0, %1, %2, %0;" : "+l"(d) : "l"(a), "l"(b));
}
__device__ __forceinline__ float f2lo(u64 v) { return __uint_as_float((unsigned)v); }
__device__ __forceinline__ float f2hi(u64 v) { return __uint_as_float((unsigned)(v >> 32)); }

// ---------------- positional encoder stage 1: R = relu(p @ W1^T + b1) ----------------
__global__ void pos_kernel(const float* __restrict__ p, const float* __restrict__ W1,
                           const float* __restrict__ b1, float* __restrict__ R) {
    int idx = blockIdx.x * blockDim.x + threadIdx.x;   // over BNR * F_DIM
    int i = idx >> 8;          // row (F_DIM = 256)
    int f = idx & 255;
    float p0 = __ldg(p + (size_t)i * 3 + 0);
    float p1 = __ldg(p + (size_t)i * 3 + 1);
    float p2 = __ldg(p + (size_t)i * 3 + 2);
    float w0 = __ldg(W1 + f * 3 + 0);
    float w1 = __ldg(W1 + f * 3 + 1);
    float w2 = __ldg(W1 + f * 3 + 2);
    float r = fmaf(p0, w0, fmaf(p1, w1, fmaf(p2, w2, __ldg(b1 + f))));
    R[idx] = fmaxf(r, 0.0f);
}

// ---------------- generic tiled GEMM, 128x128x16 tile, 8x8 micro-tile ----------------
// C[m][n] = alpha * sum_k A[m][k] * B(k,n)  (+ bias[n]) (+ addm[m][n])
// B_IS_NT:  B stored [N, K] row-major (k contiguous)  -> C = A * B^T
// !B_IS_NT: B stored [K, N] row-major (n contiguous)  -> C = A * B
#define BM 128
#define BN 128
#define BK 16
#define NT 256
#define PAD 4           // row padding: 4-way -> 2-way store conflicts

template<bool B_IS_NT, bool HAS_BIAS, bool HAS_ADD>
__global__ void __launch_bounds__(NT, 2) gemm_kernel(
    const float* __restrict__ Ag, const float* __restrict__ Bg, float* __restrict__ Cg,
    const float* __restrict__ bias, const float* __restrict__ addg,
    int M, int N, int K, size_t sA, size_t sB, size_t sC, float alpha)
{
    const float* A  = Ag + (size_t)blockIdx.z * sA;
    const float* Bm = Bg + (size_t)blockIdx.z * sB;
    float*       C  = Cg + (size_t)blockIdx.z * sC;
    const float* Xm = HAS_ADD ? (addg + (size_t)blockIdx.z * sC) : nullptr;

    __shared__ __align__(16) float As[BK][BM + PAD];   // transposed A tile: As[k][m]
    __shared__ __align__(16) float Bs[BK][BN + PAD];   // Bs[k][n]

    const int tid = threadIdx.x;
    const int tx = tid & 15;       // 0..15  -> n micro (8 cols)
    const int ty = tid >> 4;       // 0..15  -> m micro (8 rows)
    const int row0 = blockIdx.y * BM;
    const int col0 = blockIdx.x * BN;

    // global load mappings (each thread loads 8 A floats + 8 B floats per BK chunk)
    const int ar = tid >> 2;           // 0..63 (A row within tile; +64 second half)
    const int ac = (tid & 3) * 4;      // k sub-offset
    int br, bc;
    if (B_IS_NT) { br = tid >> 2; bc = (tid & 3) * 4; }     // n-row, k-col (rows br, br+64)
    else         { br = tid >> 5; bc = (tid & 31) * 4; }    // k-row, n-col (rows br, br+8)

    u64 acc[4][8];
#pragma unroll
    for (int i = 0; i < 4; i++)
#pragma unroll
        for (int j = 0; j < 8; j++) acc[i][j] = 0ull;

    float4 ra0, ra1, rb0, rb1;
    {   // prologue: stage k-chunk 0
        const float* Ab = A + (size_t)(row0 + ar) * K + ac;
        ra0 = *(const float4*)Ab;
        ra1 = *(const float4*)(Ab + (size_t)64 * K);
        if (B_IS_NT) {
            const float* Bb = Bm + (size_t)(col0 + br) * K + bc;
            rb0 = *(const float4*)Bb;
            rb1 = *(const float4*)(Bb + (size_t)64 * K);
        } else {
            rb0 = *(const float4*)(Bm + (size_t)br * N + col0 + bc);
            rb1 = *(const float4*)(Bm + (size_t)(br + 8) * N + col0 + bc);
        }
    }

    for (int kc = 0; kc < K; kc += BK) {
        // commit staged regs to smem
        As[ac + 0][ar]      = ra0.x; As[ac + 1][ar]      = ra0.y;
        As[ac + 2][ar]      = ra0.z; As[ac + 3][ar]      = ra0.w;
        As[ac + 0][ar + 64] = ra1.x; As[ac + 1][ar + 64] = ra1.y;
        As[ac + 2][ar + 64] = ra1.z; As[ac + 3][ar + 64] = ra1.w;
        if (B_IS_NT) {
            Bs[bc + 0][br]      = rb0.x; Bs[bc + 1][br]      = rb0.y;
            Bs[bc + 2][br]      = rb0.z; Bs[bc + 3][br]      = rb0.w;
            Bs[bc + 0][br + 64] = rb1.x; Bs[bc + 1][br + 64] = rb1.y;
            Bs[bc + 2][br + 64] = rb1.z; Bs[bc + 3][br + 64] = rb1.w;
        } else {
            *(float4*)&Bs[br][bc]     = rb0;
            *(float4*)&Bs[br + 8][bc] = rb1;
        }
        __syncthreads();

        const int kn = kc + BK;
        if (kn < K) {   // prefetch next chunk while computing
            const float* Ab = A + (size_t)(row0 + ar) * K + kn + ac;
            ra0 = *(const float4*)Ab;
            ra1 = *(const float4*)(Ab + (size_t)64 * K);
            if (B_IS_NT) {
                const float* Bb = Bm + (size_t)(col0 + br) * K + kn + bc;
                rb0 = *(const float4*)Bb;
                rb1 = *(const float4*)(Bb + (size_t)64 * K);
            } else {
                rb0 = *(const float4*)(Bm + (size_t)(kn + br) * N + col0 + bc);
                rb1 = *(const float4*)(Bm + (size_t)(kn + br + 8) * N + col0 + bc);
            }
        }

#pragma unroll
        for (int kk = 0; kk < BK; kk++) {
            const ulonglong2* ap = (const ulonglong2*)&As[kk][ty * 8];
            ulonglong2 av0 = ap[0], av1 = ap[1];
            u64 a0 = av0.x, a1 = av0.y, a2 = av1.x, a3 = av1.y;
            float4 bf0 = *(const float4*)&Bs[kk][tx * 8];
            float4 bf1 = *(const float4*)&Bs[kk][tx * 8 + 4];
            float bsc[8] = {bf0.x, bf0.y, bf0.z, bf0.w, bf1.x, bf1.y, bf1.z, bf1.w};
#pragma unroll
            for (int j = 0; j < 8; j++) {
                u64 bj = dupf(bsc[j]);
                ffma2(acc[0][j], a0, bj);
                ffma2(acc[1][j], a1, bj);
                ffma2(acc[2][j], a2, bj);
                ffma2(acc[3][j], a3, bj);
            }
        }
        __syncthreads();
    }

    // epilogue
    float4 bv0 = make_float4(0.f, 0.f, 0.f, 0.f);
    float4 bv1 = make_float4(0.f, 0.f, 0.f, 0.f);
    if (HAS_BIAS) {
        bv0 = *(const float4*)&bias[col0 + tx * 8];
        bv1 = *(const float4*)&bias[col0 + tx * 8 + 4];
    }
    const float bb[8] = {bv0.x, bv0.y, bv0.z, bv0.w, bv1.x, bv1.y, bv1.z, bv1.w};
#pragma unroll
    for (int i = 0; i < 4; i++) {
        const int r0 = row0 + ty * 8 + 2 * i;
        float olo[8], ohi[8];
#pragma unroll
        for (int j = 0; j < 8; j++) {
            olo[j] = f2lo(acc[i][j]) * alpha + bb[j];
            ohi[j] = f2hi(acc[i][j]) * alpha + bb[j];
        }
        if (HAS_ADD) {
            const float* x0 = &Xm[(size_t)r0 * N + col0 + tx * 8];
            const float* x1 = &Xm[(size_t)(r0 + 1) * N + col0 + tx * 8];
            float4 xa = *(const float4*)x0, xb = *(const float4*)(x0 + 4);
            float4 xc = *(const float4*)x1, xd = *(const float4*)(x1 + 4);
            olo[0] += xa.x; olo[1] += xa.y; olo[2] += xa.z; olo[3] += xa.w;
            olo[4] += xb.x; olo[5] += xb.y; olo[6] += xb.z; olo[7] += xb.w;
            ohi[0] += xc.x; ohi[1] += xc.y; ohi[2] += xc.z; ohi[3] += xc.w;
            ohi[4] += xd.x; ohi[5] += xd.y; ohi[6] += xd.z; ohi[7] += xd.w;
        }
        float* c0 = &C[(size_t)r0 * N + col0 + tx * 8];
        float* c1 = &C[(size_t)(r0 + 1) * N + col0 + tx * 8];
        *(float4*)c0       = make_float4(olo[0], olo[1], olo[2], olo[3]);
        *(float4*)(c0 + 4) = make_float4(olo[4], olo[5], olo[6], olo[7]);
        *(float4*)c1       = make_float4(ohi[0], ohi[1], ohi[2], ohi[3]);
        *(float4*)(c1 + 4) = make_float4(ohi[4], ohi[5], ohi[6], ohi[7]);
    }
}

// ---------------- rowwise softmax over N_SEQ = 2048 (one block per row) ----------------
__global__ void softmax_kernel(float* __restrict__ S) {
    __shared__ float red[8];
    const size_t row = blockIdx.x;
    float4* r = (float4*)(S + row * (size_t)N_SEQ);
    const int tid = threadIdx.x;        // 256 threads, 8 floats each
    float4 v0 = r[tid * 2], v1 = r[tid * 2 + 1];

    float m = fmaxf(fmaxf(fmaxf(v0.x, v0.y), fmaxf(v0.z, v0.w)),
                    fmaxf(fmaxf(v1.x, v1.y), fmaxf(v1.z, v1.w)));
#pragma unroll
    for (int o = 16; o; o >>= 1) m = fmaxf(m, __shfl_xor_sync(0xffffffffu, m, o));
    if ((tid & 31) == 0) red[tid >> 5] = m;
    __syncthreads();
    float mm = red[0];
#pragma unroll
    for (int i = 1; i < 8; i++) mm = fmaxf(mm, red[i]);
    __syncthreads();   // before red reuse

    v0.x = __expf(v0.x - mm); v0.y = __expf(v0.y - mm);
    v0.z = __expf(v0.z - mm); v0.w = __expf(v0.w - mm);
    v1.x = __expf(v1.x - mm); v1.y = __expf(v1.y - mm);
    v1.z = __expf(v1.z - mm); v1.w = __expf(v1.w - mm);

    float s = ((v0.x + v0.y) + (v0.z + v0.w)) + ((v1.x + v1.y) + (v1.z + v1.w));
#pragma unroll
    for (int o = 16; o; o >>= 1) s += __shfl_xor_sync(0xffffffffu, s, o);
    if ((tid & 31) == 0) red[tid >> 5] = s;
    __syncthreads();
    float tot = ((red[0] + red[1]) + (red[2] + red[3])) +
                ((red[4] + red[5]) + (red[6] + red[7]));
    float inv = __frcp_rn(tot);

    v0.x *= inv; v0.y *= inv; v0.z *= inv; v0.w *= inv;
    v1.x *= inv; v1.y *= inv; v1.z *= inv; v1.w *= inv;
    r[tid * 2] = v0; r[tid * 2 + 1] = v1;
}

// ---------------- launch ----------------
extern "C" void kernel_launch(void* const* d_in, const int* in_sizes, int n_in,
                              void* d_out, int out_size) {
    const float* x  = (const float*)d_in[0];
    const float* p  = (const float*)d_in[1];
    const float* Wq = (const float*)d_in[2];
    const float* bq = (const float*)d_in[3];
    const float* Wk = (const float*)d_in[4];
    const float* bk = (const float*)d_in[5];
    const float* Wv = (const float*)d_in[6];
    const float* bv = (const float*)d_in[7];
    const float* W1 = (const float*)d_in[8];
    const float* b1 = (const float*)d_in[9];
    const float* W2 = (const float*)d_in[10];
    const float* b2 = (const float*)d_in[11];
    float* out = (float*)d_out;

    float *hbuf, *qbuf, *kbuf, *vbuf, *sbuf;
    cudaGetSymbolAddress((void**)&hbuf, g_h);
    cudaGetSymbolAddress((void**)&qbuf, g_q);
    cudaGetSymbolAddress((void**)&kbuf, g_k);
    cudaGetSymbolAddress((void**)&vbuf, g_v);
    cudaGetSymbolAddress((void**)&sbuf, g_s);

    // 1) R = relu(p @ W1^T + b1)   (R temporarily in g_q)
    pos_kernel<<<(BNR * F_DIM) / 256, 256>>>(p, W1, b1, qbuf);

    // 2) H = R @ W2^T + b2 + x
    gemm_kernel<true, true, true><<<dim3(F_DIM / BN, BNR / BM, 1), NT>>>(
        qbuf, W2, hbuf, b2, x, BNR, F_DIM, F_DIM, 0, 0, 0, 1.0f);

    // 3) QKV projections (note the reference swaps: q uses Wk/bk, k uses Wq/bq)
    gemm_kernel<true, true, false><<<dim3(F_DIM / BN, BNR / BM, 1), NT>>>(
        hbuf, Wk, qbuf, bk, nullptr, BNR, F_DIM, F_DIM, 0, 0, 0, 1.0f);
    gemm_kernel<true, true, false><<<dim3(F_DIM / BN, BNR / BM, 1), NT>>>(
        hbuf, Wq, kbuf, bq, nullptr, BNR, F_DIM, F_DIM, 0, 0, 0, 1.0f);
    gemm_kernel<true, true, false><<<dim3(F_DIM / BN, BNR / BM, 1), NT>>>(
        hbuf, Wv, vbuf, bv, nullptr, BNR, F_DIM, F_DIM, 0, 0, 0, 1.0f);

    // 4) S[b] = (Q[b] @ K[b]^T) / 16
    gemm_kernel<true, false, false><<<dim3(N_SEQ / BN, N_SEQ / BM, B_SZ), NT>>>(
        qbuf, kbuf, sbuf, nullptr, nullptr, N_SEQ, N_SEQ, F_DIM,
        (size_t)N_SEQ * F_DIM, (size_t)N_SEQ * F_DIM, (size_t)N_SEQ * N_SEQ, 0.0625f);

    // 5) rowwise softmax
    softmax_kernel<<<B_SZ * N_SEQ, 256>>>(sbuf);

    // 6) out[b] = P[b] @ V[b]
    gemm_kernel<false, false, false><<<dim3(F_DIM / BN, N_SEQ / BM, B_SZ), NT>>>(
        sbuf, vbuf, out, nullptr, nullptr, N_SEQ, F_DIM, N_SEQ,
        (size_t)N_SEQ * N_SEQ, (size_t)N_SEQ * F_DIM, (size_t)N_SEQ * F_DIM, 1.0f);
}

// round 5
// speedup vs baseline: 1.1687x; 1.1687x over previous
#include <cuda_runtime.h>

typedef unsigned long long u64;

#define B_SZ   16
#define N_SEQ  2048
#define F_DIM  256
#define BNR    (B_SZ * N_SEQ)   // 32768 rows

// ---------------- device scratch (no runtime allocation allowed) ----------------
__device__ float g_h[(size_t)BNR * F_DIM];
__device__ float g_q[(size_t)BNR * F_DIM];                 // also reused as R temp
__device__ float g_k[(size_t)BNR * F_DIM];
__device__ float g_v[(size_t)BNR * F_DIM];
__device__ float g_s[(size_t)B_SZ * N_SEQ * N_SEQ];        // 268 MB scores

// ---------------- packed f32x2 helpers (Blackwell 2xFP32 path) ----------------
__device__ __forceinline__ u64 dupf(float x) {
    u64 r; unsigned xi = __float_as_uint(x);
    asm("mov.b64 %0, {%1,%1};" : "=l"(r) : "r"(xi));
    return r;
}
__device__ __forceinline__ void ffma2(u64& d, u64 a, u64 b) {
    asm("fma.rn.f32x2 %0, %1, %2, %0;" : "+l"(d) : "l"(a), "l"(b));
}
__device__ __forceinline__ float f2lo(u64 v) { return __uint_as_float((unsigned)v); }
__device__ __forceinline__ float f2hi(u64 v) { return __uint_as_float((unsigned)(v >> 32)); }

// ---------------- positional encoder stage 1: R = relu(p @ W1^T + b1) ----------------
__global__ void pos_kernel(const float* __restrict__ p, const float* __restrict__ W1,
                           const float* __restrict__ b1, float* __restrict__ R) {
    int idx = blockIdx.x * blockDim.x + threadIdx.x;
    int i = idx >> 8;
    int f = idx & 255;
    float p0 = __ldg(p + (size_t)i * 3 + 0);
    float p1 = __ldg(p + (size_t)i * 3 + 1);
    float p2 = __ldg(p + (size_t)i * 3 + 2);
    float w0 = __ldg(W1 + f * 3 + 0);
    float w1 = __ldg(W1 + f * 3 + 1);
    float w2 = __ldg(W1 + f * 3 + 2);
    float r = fmaf(p0, w0, fmaf(p1, w1, fmaf(p2, w2, __ldg(b1 + f))));
    R[idx] = fmaxf(r, 0.0f);
}

// ---------------- generic tiled GEMM, 128x128x16 tile, 8x8 micro (4+4 split) --------
// C[m][n] = alpha * sum_k A[m][k] * B(k,n)  (+ bias[n]) (+ addm[m][n])
// B_IS_NT:  B stored [N, K] row-major -> C = A * B^T
// !B_IS_NT: B stored [K, N] row-major -> C = A * B
#define BM 128
#define BN 128
#define BK 16
#define NT 256
#define PAD 4

template<bool B_IS_NT, bool HAS_BIAS, bool HAS_ADD>
__global__ void __launch_bounds__(NT) gemm_kernel(
    const float* __restrict__ Ag, const float* __restrict__ Bg, float* __restrict__ Cg,
    const float* __restrict__ bias, const float* __restrict__ addg,
    int M, int N, int K, size_t sA, size_t sB, size_t sC, float alpha)
{
    const float* A  = Ag + (size_t)blockIdx.z * sA;
    const float* Bm = Bg + (size_t)blockIdx.z * sB;
    float*       C  = Cg + (size_t)blockIdx.z * sC;
    const float* Xm = HAS_ADD ? (addg + (size_t)blockIdx.z * sC) : nullptr;

    __shared__ __align__(16) float As[2][BK][BM + PAD];   // transposed A: As[buf][k][m]
    __shared__ __align__(16) float Bs[2][BK][BN + PAD];   // Bs[buf][k][n]

    const int tid = threadIdx.x;
    const int tx = tid & 15;       // n micro: cols tx*4.. and 64+tx*4..
    const int ty = tid >> 4;       // m micro: rows ty*4.. and 64+ty*4..
    const int row0 = blockIdx.y * BM;
    const int col0 = blockIdx.x * BN;

    // global load mappings (each thread stages 8 A floats + 8 B floats per chunk)
    const int ar = tid >> 2;           // 0..63 (A rows ar, ar+64)
    const int ac = (tid & 3) * 4;      // k sub-offset
    int br, bc;
    if (B_IS_NT) { br = tid >> 2; bc = (tid & 3) * 4; }
    else         { br = tid >> 5; bc = (tid & 31) * 4; }

    u64 acc[4][8];
#pragma unroll
    for (int i = 0; i < 4; i++)
#pragma unroll
        for (int j = 0; j < 8; j++) acc[i][j] = 0ull;

    float4 ra0, ra1, rb0, rb1;
    {   // prologue: stage chunk 0 and commit to buffer 0
        const float* Ab = A + (size_t)(row0 + ar) * K + ac;
        ra0 = *(const float4*)Ab;
        ra1 = *(const float4*)(Ab + (size_t)64 * K);
        if (B_IS_NT) {
            const float* Bb = Bm + (size_t)(col0 + br) * K + bc;
            rb0 = *(const float4*)Bb;
            rb1 = *(const float4*)(Bb + (size_t)64 * K);
        } else {
            rb0 = *(const float4*)(Bm + (size_t)br * N + col0 + bc);
            rb1 = *(const float4*)(Bm + (size_t)(br + 8) * N + col0 + bc);
        }
        As[0][ac + 0][ar]      = ra0.x; As[0][ac + 1][ar]      = ra0.y;
        As[0][ac + 2][ar]      = ra0.z; As[0][ac + 3][ar]      = ra0.w;
        As[0][ac + 0][ar + 64] = ra1.x; As[0][ac + 1][ar + 64] = ra1.y;
        As[0][ac + 2][ar + 64] = ra1.z; As[0][ac + 3][ar + 64] = ra1.w;
        if (B_IS_NT) {
            Bs[0][bc + 0][br]      = rb0.x; Bs[0][bc + 1][br]      = rb0.y;
            Bs[0][bc + 2][br]      = rb0.z; Bs[0][bc + 3][br]      = rb0.w;
            Bs[0][bc + 0][br + 64] = rb1.x; Bs[0][bc + 1][br + 64] = rb1.y;
            Bs[0][bc + 2][br + 64] = rb1.z; Bs[0][bc + 3][br + 64] = rb1.w;
        } else {
            *(float4*)&Bs[0][br][bc]     = rb0;
            *(float4*)&Bs[0][br + 8][bc] = rb1;
        }
        __syncthreads();
    }

    int buf = 0;
    for (int kc = 0; kc < K; kc += BK) {
        const int kn = kc + BK;
        const bool more = (kn < K);
        if (more) {   // prefetch next chunk into regs (latency hidden by compute)
            const float* Ab = A + (size_t)(row0 + ar) * K + kn + ac;
            ra0 = *(const float4*)Ab;
            ra1 = *(const float4*)(Ab + (size_t)64 * K);
            if (B_IS_NT) {
                const float* Bb = Bm + (size_t)(col0 + br) * K + kn + bc;
                rb0 = *(const float4*)Bb;
                rb1 = *(const float4*)(Bb + (size_t)64 * K);
            } else {
                rb0 = *(const float4*)(Bm + (size_t)(kn + br) * N + col0 + bc);
                rb1 = *(const float4*)(Bm + (size_t)(kn + br + 8) * N + col0 + bc);
            }
        }

#pragma unroll
        for (int kk = 0; kk < BK; kk++) {
            ulonglong2 av0 = *(const ulonglong2*)&As[buf][kk][ty * 4];
            ulonglong2 av1 = *(const ulonglong2*)&As[buf][kk][64 + ty * 4];
            u64 a0 = av0.x, a1 = av0.y, a2 = av1.x, a3 = av1.y;
            float4 bf0 = *(const float4*)&Bs[buf][kk][tx * 4];
            float4 bf1 = *(const float4*)&Bs[buf][kk][64 + tx * 4];
            u64 b0 = dupf(bf0.x), b1 = dupf(bf0.y), b2 = dupf(bf0.z), b3 = dupf(bf0.w);
            u64 b4 = dupf(bf1.x), b5 = dupf(bf1.y), b6 = dupf(bf1.z), b7 = dupf(bf1.w);
            ffma2(acc[0][0], a0, b0); ffma2(acc[1][0], a1, b0);
            ffma2(acc[2][0], a2, b0); ffma2(acc[3][0], a3, b0);
            ffma2(acc[0][1], a0, b1); ffma2(acc[1][1], a1, b1);
            ffma2(acc[2][1], a2, b1); ffma2(acc[3][1], a3, b1);
            ffma2(acc[0][2], a0, b2); ffma2(acc[1][2], a1, b2);
            ffma2(acc[2][2], a2, b2); ffma2(acc[3][2], a3, b2);
            ffma2(acc[0][3], a0, b3); ffma2(acc[1][3], a1, b3);
            ffma2(acc[2][3], a2, b3); ffma2(acc[3][3], a3, b3);
            ffma2(acc[0][4], a0, b4); ffma2(acc[1][4], a1, b4);
            ffma2(acc[2][4], a2, b4); ffma2(acc[3][4], a3, b4);
            ffma2(acc[0][5], a0, b5); ffma2(acc[1][5], a1, b5);
            ffma2(acc[2][5], a2, b5); ffma2(acc[3][5], a3, b5);
            ffma2(acc[0][6], a0, b6); ffma2(acc[1][6], a1, b6);
            ffma2(acc[2][6], a2, b6); ffma2(acc[3][6], a3, b6);
            ffma2(acc[0][7], a0, b7); ffma2(acc[1][7], a1, b7);
            ffma2(acc[2][7], a2, b7); ffma2(acc[3][7], a3, b7);
        }

        if (more) {   // commit to the other buffer; single barrier per chunk
            const int nb = buf ^ 1;
            As[nb][ac + 0][ar]      = ra0.x; As[nb][ac + 1][ar]      = ra0.y;
            As[nb][ac + 2][ar]      = ra0.z; As[nb][ac + 3][ar]      = ra0.w;
            As[nb][ac + 0][ar + 64] = ra1.x; As[nb][ac + 1][ar + 64] = ra1.y;
            As[nb][ac + 2][ar + 64] = ra1.z; As[nb][ac + 3][ar + 64] = ra1.w;
            if (B_IS_NT) {
                Bs[nb][bc + 0][br]      = rb0.x; Bs[nb][bc + 1][br]      = rb0.y;
                Bs[nb][bc + 2][br]      = rb0.z; Bs[nb][bc + 3][br]      = rb0.w;
                Bs[nb][bc + 0][br + 64] = rb1.x; Bs[nb][bc + 1][br + 64] = rb1.y;
                Bs[nb][bc + 2][br + 64] = rb1.z; Bs[nb][bc + 3][br + 64] = rb1.w;
            } else {
                *(float4*)&Bs[nb][br][bc]     = rb0;
                *(float4*)&Bs[nb][br + 8][bc] = rb1;
            }
            buf = nb;
            __syncthreads();
        }
    }

    // ---------------- epilogue (4+4 split in both m and n) ----------------
    float bb[8];
    if (HAS_BIAS) {
        float4 bv0 = *(const float4*)&bias[col0 + tx * 4];
        float4 bv1 = *(const float4*)&bias[col0 + 64 + tx * 4];
        bb[0] = bv0.x; bb[1] = bv0.y; bb[2] = bv0.z; bb[3] = bv0.w;
        bb[4] = bv1.x; bb[5] = bv1.y; bb[6] = bv1.z; bb[7] = bv1.w;
    } else {
#pragma unroll
        for (int j = 0; j < 8; j++) bb[j] = 0.0f;
    }
#pragma unroll
    for (int ih = 0; ih < 2; ih++) {
#pragma unroll
        for (int ip = 0; ip < 2; ip++) {
            const int i = ih * 2 + ip;
            const int r0 = row0 + ih * 64 + ty * 4 + 2 * ip;
            float olo[8], ohi[8];
#pragma unroll
            for (int j = 0; j < 8; j++) {
                olo[j] = f2lo(acc[i][j]) * alpha + bb[j];
                ohi[j] = f2hi(acc[i][j]) * alpha + bb[j];
            }
#pragma unroll
            for (int jh = 0; jh < 2; jh++) {
                const int c = col0 + jh * 64 + tx * 4;
                if (HAS_ADD) {
                    float4 x0 = *(const float4*)&Xm[(size_t)r0 * N + c];
                    float4 x1 = *(const float4*)&Xm[(size_t)(r0 + 1) * N + c];
                    olo[jh*4+0] += x0.x; olo[jh*4+1] += x0.y;
                    olo[jh*4+2] += x0.z; olo[jh*4+3] += x0.w;
                    ohi[jh*4+0] += x1.x; ohi[jh*4+1] += x1.y;
                    ohi[jh*4+2] += x1.z; ohi[jh*4+3] += x1.w;
                }
                *(float4*)&C[(size_t)r0 * N + c] =
                    make_float4(olo[jh*4+0], olo[jh*4+1], olo[jh*4+2], olo[jh*4+3]);
                *(float4*)&C[(size_t)(r0 + 1) * N + c] =
                    make_float4(ohi[jh*4+0], ohi[jh*4+1], ohi[jh*4+2], ohi[jh*4+3]);
            }
        }
    }
}

// ---------------- rowwise softmax over N_SEQ = 2048 (one block per row) ----------------
__global__ void softmax_kernel(float* __restrict__ S) {
    __shared__ float red[8];
    const size_t row = blockIdx.x;
    float4* r = (float4*)(S + row * (size_t)N_SEQ);
    const int tid = threadIdx.x;        // 256 threads, 8 floats each
    float4 v0 = r[tid * 2], v1 = r[tid * 2 + 1];

    float m = fmaxf(fmaxf(fmaxf(v0.x, v0.y), fmaxf(v0.z, v0.w)),
                    fmaxf(fmaxf(v1.x, v1.y), fmaxf(v1.z, v1.w)));
#pragma unroll
    for (int o = 16; o; o >>= 1) m = fmaxf(m, __shfl_xor_sync(0xffffffffu, m, o));
    if ((tid & 31) == 0) red[tid >> 5] = m;
    __syncthreads();
    float mm = red[0];
#pragma unroll
    for (int i = 1; i < 8; i++) mm = fmaxf(mm, red[i]);
    __syncthreads();

    v0.x = __expf(v0.x - mm); v0.y = __expf(v0.y - mm);
    v0.z = __expf(v0.z - mm); v0.w = __expf(v0.w - mm);
    v1.x = __expf(v1.x - mm); v1.y = __expf(v1.y - mm);
    v1.z = __expf(v1.z - mm); v1.w = __expf(v1.w - mm);

    float s = ((v0.x + v0.y) + (v0.z + v0.w)) + ((v1.x + v1.y) + (v1.z + v1.w));
#pragma unroll
    for (int o = 16; o; o >>= 1) s += __shfl_xor_sync(0xffffffffu, s, o);
    if ((tid & 31) == 0) red[tid >> 5] = s;
    __syncthreads();
    float tot = ((red[0] + red[1]) + (red[2] + red[3])) +
                ((red[4] + red[5]) + (red[6] + red[7]));
    float inv = __frcp_rn(tot);

    v0.x *= inv; v0.y *= inv; v0.z *= inv; v0.w *= inv;
    v1.x *= inv; v1.y *= inv; v1.z *= inv; v1.w *= inv;
    r[tid * 2] = v0; r[tid * 2 + 1] = v1;
}

// ---------------- launch ----------------
extern "C" void kernel_launch(void* const* d_in, const int* in_sizes, int n_in,
                              void* d_out, int out_size) {
    const float* x  = (const float*)d_in[0];
    const float* p  = (const float*)d_in[1];
    const float* Wq = (const float*)d_in[2];
    const float* bq = (const float*)d_in[3];
    const float* Wk = (const float*)d_in[4];
    const float* bk = (const float*)d_in[5];
    const float* Wv = (const float*)d_in[6];
    const float* bv = (const float*)d_in[7];
    const float* W1 = (const float*)d_in[8];
    const float* b1 = (const float*)d_in[9];
    const float* W2 = (const float*)d_in[10];
    const float* b2 = (const float*)d_in[11];
    float* out = (float*)d_out;

    float *hbuf, *qbuf, *kbuf, *vbuf, *sbuf;
    cudaGetSymbolAddress((void**)&hbuf, g_h);
    cudaGetSymbolAddress((void**)&qbuf, g_q);
    cudaGetSymbolAddress((void**)&kbuf, g_k);
    cudaGetSymbolAddress((void**)&vbuf, g_v);
    cudaGetSymbolAddress((void**)&sbuf, g_s);

    // 1) R = relu(p @ W1^T + b1)   (R temporarily in g_q)
    pos_kernel<<<(BNR * F_DIM) / 256, 256>>>(p, W1, b1, qbuf);

    // 2) H = R @ W2^T + b2 + x
    gemm_kernel<true, true, true><<<dim3(F_DIM / BN, BNR / BM, 1), NT>>>(
        qbuf, W2, hbuf, b2, x, BNR, F_DIM, F_DIM, 0, 0, 0, 1.0f);

    // 3) QKV projections (reference swaps: q uses Wk/bk, k uses Wq/bq)
    gemm_kernel<true, true, false><<<dim3(F_DIM / BN, BNR / BM, 1), NT>>>(
        hbuf, Wk, qbuf, bk, nullptr, BNR, F_DIM, F_DIM, 0, 0, 0, 1.0f);
    gemm_kernel<true, true, false><<<dim3(F_DIM / BN, BNR / BM, 1), NT>>>(
        hbuf, Wq, kbuf, bq, nullptr, BNR, F_DIM, F_DIM, 0, 0, 0, 1.0f);
    gemm_kernel<true, true, false><<<dim3(F_DIM / BN, BNR / BM, 1), NT>>>(
        hbuf, Wv, vbuf, bv, nullptr, BNR, F_DIM, F_DIM, 0, 0, 0, 1.0f);

    // 4) S[b] = (Q[b] @ K[b]^T) / 16
    gemm_kernel<true, false, false><<<dim3(N_SEQ / BN, N_SEQ / BM, B_SZ), NT>>>(
        qbuf, kbuf, sbuf, nullptr, nullptr, N_SEQ, N_SEQ, F_DIM,
        (size_t)N_SEQ * F_DIM, (size_t)N_SEQ * F_DIM, (size_t)N_SEQ * N_SEQ, 0.0625f);

    // 5) rowwise softmax
    softmax_kernel<<<B_SZ * N_SEQ, 256>>>(sbuf);

    // 6) out[b] = P[b] @ V[b]
    gemm_kernel<false, false, false><<<dim3(F_DIM / BN, N_SEQ / BM, B_SZ), NT>>>(
        sbuf, vbuf, out, nullptr, nullptr, N_SEQ, F_DIM, N_SEQ,
        (size_t)N_SEQ * N_SEQ, (size_t)N_SEQ * F_DIM, (size_t)N_SEQ * F_DIM, 1.0f);
}

// round 11
// speedup vs baseline: 1.5424x; 1.3198x over previous
#include <cuda_runtime.h>
#include <cuda_bf16.h>
#include <cstdint>

typedef unsigned long long u64;

#define B_SZ   16
#define N_SEQ  2048
#define F_DIM  256
#define BNR    (B_SZ * N_SEQ)   // 32768 rows

// ---------------- device scratch (no runtime allocation allowed) ----------------
__device__ float g_h[(size_t)BNR * F_DIM];
__device__ float g_q[(size_t)BNR * F_DIM];                 // also reused as R temp
__device__ float g_k[(size_t)BNR * F_DIM];
__device__ float g_v[(size_t)BNR * F_DIM];
__device__ float g_s[(size_t)B_SZ * N_SEQ * N_SEQ];        // 268 MB scores (fp32)
__device__ __nv_bfloat16 g_qh[(size_t)BNR * F_DIM];
__device__ __nv_bfloat16 g_ql[(size_t)BNR * F_DIM];
__device__ __nv_bfloat16 g_kh[(size_t)BNR * F_DIM];
__device__ __nv_bfloat16 g_kl[(size_t)BNR * F_DIM];
__device__ __nv_bfloat16 g_vth[(size_t)F_DIM * BNR];       // V^T hi  [F][BNR]
__device__ __nv_bfloat16 g_vtl[(size_t)F_DIM * BNR];       // V^T lo
__device__ __nv_bfloat16 g_ph[(size_t)B_SZ * N_SEQ * N_SEQ];
__device__ __nv_bfloat16 g_pl[(size_t)B_SZ * N_SEQ * N_SEQ];

// ---------------- packed f32x2 helpers (Blackwell 2xFP32 path) ----------------
__device__ __forceinline__ u64 dupf(float x) {
    u64 r; unsigned xi = __float_as_uint(x);
    asm("mov.b64 %0, {%1,%1};" : "=l"(r) : "r"(xi));
    return r;
}
__device__ __forceinline__ void ffma2(u64& d, u64 a, u64 b) {
    asm("fma.rn.f32x2 %0, %1, %2, %0;" : "+l"(d) : "l"(a), "l"(b));
}
__device__ __forceinline__ float f2lo(u64 v) { return __uint_as_float((unsigned)v); }
__device__ __forceinline__ float f2hi(u64 v) { return __uint_as_float((unsigned)(v >> 32)); }

// ---------------- warp-MMA helpers (sm_80+ baseline; valid on compute_103) ----
__device__ __forceinline__ uint32_t smem_u32(const void* p) {
    uint32_t a;
    asm("{ .reg .u64 t; cvta.to.shared.u64 t, %1; cvt.u32.u64 %0, t; }" : "=r"(a) : "l"(p));
    return a;
}
__device__ __forceinline__ void cp16(uint32_t s, const void* g) {
    asm volatile("cp.async.cg.shared.global [%0], [%1], 16;" :: "r"(s), "l"(g) : "memory");
}
template<int N> __device__ __forceinline__ void cp_wait() {
    asm volatile("cp.async.wait_group %0;" :: "n"(N) : "memory");
}
__device__ __forceinline__ void cp_commit() {
    asm volatile("cp.async.commit_group;" ::: "memory");
}
__device__ __forceinline__ uint32_t lds32(uint32_t a) {
    uint32_t v;
    asm volatile("ld.shared.b32 %0, [%1];" : "=r"(v) : "r"(a));
    return v;
}
__device__ __forceinline__ void mma16816(float* c, const uint32_t* a, const uint32_t* b) {
    asm volatile(
        "mma.sync.aligned.m16n8k16.row.col.f32.bf16.bf16.f32 "
        "{%0,%1,%2,%3}, {%4,%5,%6,%7}, {%8,%9}, {%0,%1,%2,%3};"
        : "+f"(c[0]), "+f"(c[1]), "+f"(c[2]), "+f"(c[3])
        : "r"(a[0]), "r"(a[1]), "r"(a[2]), "r"(a[3]), "r"(b[0]), "r"(b[1]));
}

// ---------------- positional encoder stage 1: R = relu(p @ W1^T + b1) ----------------
__global__ void pos_kernel(const float* __restrict__ p, const float* __restrict__ W1,
                           const float* __restrict__ b1, float* __restrict__ R) {
    int idx = blockIdx.x * blockDim.x + threadIdx.x;
    int i = idx >> 8;
    int f = idx & 255;
    float p0 = __ldg(p + (size_t)i * 3 + 0);
    float p1 = __ldg(p + (size_t)i * 3 + 1);
    float p2 = __ldg(p + (size_t)i * 3 + 2);
    float w0 = __ldg(W1 + f * 3 + 0);
    float w1 = __ldg(W1 + f * 3 + 1);
    float w2 = __ldg(W1 + f * 3 + 2);
    float r = fmaf(p0, w0, fmaf(p1, w1, fmaf(p2, w2, __ldg(b1 + f))));
    R[idx] = fmaxf(r, 0.0f);
}

// ---------------- fp32 tiled GEMM (projections), 128x128x16, 8x8 micro ----------------
#define BM 128
#define BN 128
#define BK 16
#define NT 256
#define PAD 4

template<bool B_IS_NT, bool HAS_BIAS, bool HAS_ADD>
__global__ void __launch_bounds__(NT) gemm_kernel(
    const float* __restrict__ Ag, const float* __restrict__ Bg, float* __restrict__ Cg,
    const float* __restrict__ bias, const float* __restrict__ addg,
    int M, int N, int K, size_t sA, size_t sB, size_t sC, float alpha)
{
    const float* A  = Ag + (size_t)blockIdx.z * sA;
    const float* Bm = Bg + (size_t)blockIdx.z * sB;
    float*       C  = Cg + (size_t)blockIdx.z * sC;
    const float* Xm = HAS_ADD ? (addg + (size_t)blockIdx.z * sC) : nullptr;

    __shared__ __align__(16) float As[2][BK][BM + PAD];
    __shared__ __align__(16) float Bs[2][BK][BN + PAD];

    const int tid = threadIdx.x;
    const int tx = tid & 15;
    const int ty = tid >> 4;
    const int row0 = blockIdx.y * BM;
    const int col0 = blockIdx.x * BN;

    const int ar = tid >> 2;
    const int ac = (tid & 3) * 4;
    int br, bc;
    if (B_IS_NT) { br = tid >> 2; bc = (tid & 3) * 4; }
    else         { br = tid >> 5; bc = (tid & 31) * 4; }

    u64 acc[4][8];
#pragma unroll
    for (int i = 0; i < 4; i++)
#pragma unroll
        for (int j = 0; j < 8; j++) acc[i][j] = 0ull;

    float4 ra0, ra1, rb0, rb1;
    {
        const float* Ab = A + (size_t)(row0 + ar) * K + ac;
        ra0 = *(const float4*)Ab;
        ra1 = *(const float4*)(Ab + (size_t)64 * K);
        if (B_IS_NT) {
            const float* Bb = Bm + (size_t)(col0 + br) * K + bc;
            rb0 = *(const float4*)Bb;
            rb1 = *(const float4*)(Bb + (size_t)64 * K);
        } else {
            rb0 = *(const float4*)(Bm + (size_t)br * N + col0 + bc);
            rb1 = *(const float4*)(Bm + (size_t)(br + 8) * N + col0 + bc);
        }
        As[0][ac + 0][ar]      = ra0.x; As[0][ac + 1][ar]      = ra0.y;
        As[0][ac + 2][ar]      = ra0.z; As[0][ac + 3][ar]      = ra0.w;
        As[0][ac + 0][ar + 64] = ra1.x; As[0][ac + 1][ar + 64] = ra1.y;
        As[0][ac + 2][ar + 64] = ra1.z; As[0][ac + 3][ar + 64] = ra1.w;
        if (B_IS_NT) {
            Bs[0][bc + 0][br]      = rb0.x; Bs[0][bc + 1][br]      = rb0.y;
            Bs[0][bc + 2][br]      = rb0.z; Bs[0][bc + 3][br]      = rb0.w;
            Bs[0][bc + 0][br + 64] = rb1.x; Bs[0][bc + 1][br + 64] = rb1.y;
            Bs[0][bc + 2][br + 64] = rb1.z; Bs[0][bc + 3][br + 64] = rb1.w;
        } else {
            *(float4*)&Bs[0][br][bc]     = rb0;
            *(float4*)&Bs[0][br + 8][bc] = rb1;
        }
        __syncthreads();
    }

    int buf = 0;
    for (int kc = 0; kc < K; kc += BK) {
        const int kn = kc + BK;
        const bool more = (kn < K);
        if (more) {
            const float* Ab = A + (size_t)(row0 + ar) * K + kn + ac;
            ra0 = *(const float4*)Ab;
            ra1 = *(const float4*)(Ab + (size_t)64 * K);
            if (B_IS_NT) {
                const float* Bb = Bm + (size_t)(col0 + br) * K + kn + bc;
                rb0 = *(const float4*)Bb;
                rb1 = *(const float4*)(Bb + (size_t)64 * K);
            } else {
                rb0 = *(const float4*)(Bm + (size_t)(kn + br) * N + col0 + bc);
                rb1 = *(const float4*)(Bm + (size_t)(kn + br + 8) * N + col0 + bc);
            }
        }

#pragma unroll
        for (int kk = 0; kk < BK; kk++) {
            ulonglong2 av0 = *(const ulonglong2*)&As[buf][kk][ty * 4];
            ulonglong2 av1 = *(const ulonglong2*)&As[buf][kk][64 + ty * 4];
            u64 a0 = av0.x, a1 = av0.y, a2 = av1.x, a3 = av1.y;
            float4 bf0 = *(const float4*)&Bs[buf][kk][tx * 4];
            float4 bf1 = *(const float4*)&Bs[buf][kk][64 + tx * 4];
            u64 b0 = dupf(bf0.x), b1 = dupf(bf0.y), b2 = dupf(bf0.z), b3 = dupf(bf0.w);
            u64 b4 = dupf(bf1.x), b5 = dupf(bf1.y), b6 = dupf(bf1.z), b7 = dupf(bf1.w);
            ffma2(acc[0][0], a0, b0); ffma2(acc[1][0], a1, b0);
            ffma2(acc[2][0], a2, b0); ffma2(acc[3][0], a3, b0);
            ffma2(acc[0][1], a0, b1); ffma2(acc[1][1], a1, b1);
            ffma2(acc[2][1], a2, b1); ffma2(acc[3][1], a3, b1);
            ffma2(acc[0][2], a0, b2); ffma2(acc[1][2], a1, b2);
            ffma2(acc[2][2], a2, b2); ffma2(acc[3][2], a3, b2);
            ffma2(acc[0][3], a0, b3); ffma2(acc[1][3], a1, b3);
            ffma2(acc[2][3], a2, b3); ffma2(acc[3][3], a3, b3);
            ffma2(acc[0][4], a0, b4); ffma2(acc[1][4], a1, b4);
            ffma2(acc[2][4], a2, b4); ffma2(acc[3][4], a3, b4);
            ffma2(acc[0][5], a0, b5); ffma2(acc[1][5], a1, b5);
            ffma2(acc[2][5], a2, b5); ffma2(acc[3][5], a3, b5);
            ffma2(acc[0][6], a0, b6); ffma2(acc[1][6], a1, b6);
            ffma2(acc[2][6], a2, b6); ffma2(acc[3][6], a3, b6);
            ffma2(acc[0][7], a0, b7); ffma2(acc[1][7], a1, b7);
            ffma2(acc[2][7], a2, b7); ffma2(acc[3][7], a3, b7);
        }

        if (more) {
            const int nb = buf ^ 1;
            As[nb][ac + 0][ar]      = ra0.x; As[nb][ac + 1][ar]      = ra0.y;
            As[nb][ac + 2][ar]      = ra0.z; As[nb][ac + 3][ar]      = ra0.w;
            As[nb][ac + 0][ar + 64] = ra1.x; As[nb][ac + 1][ar + 64] = ra1.y;
            As[nb][ac + 2][ar + 64] = ra1.z; As[nb][ac + 3][ar + 64] = ra1.w;
            if (B_IS_NT) {
                Bs[nb][bc + 0][br]      = rb0.x; Bs[nb][bc + 1][br]      = rb0.y;
                Bs[nb][bc + 2][br]      = rb0.z; Bs[nb][bc + 3][br]      = rb0.w;
                Bs[nb][bc + 0][br + 64] = rb1.x; Bs[nb][bc + 1][br + 64] = rb1.y;
                Bs[nb][bc + 2][br + 64] = rb1.z; Bs[nb][bc + 3][br + 64] = rb1.w;
            } else {
                *(float4*)&Bs[nb][br][bc]     = rb0;
                *(float4*)&Bs[nb][br + 8][bc] = rb1;
            }
            buf = nb;
            __syncthreads();
        }
    }

    float bb[8];
    if (HAS_BIAS) {
        float4 bv0 = *(const float4*)&bias[col0 + tx * 4];
        float4 bv1 = *(const float4*)&bias[col0 + 64 + tx * 4];
        bb[0] = bv0.x; bb[1] = bv0.y; bb[2] = bv0.z; bb[3] = bv0.w;
        bb[4] = bv1.x; bb[5] = bv1.y; bb[6] = bv1.z; bb[7] = bv1.w;
    } else {
#pragma unroll
        for (int j = 0; j < 8; j++) bb[j] = 0.0f;
    }
#pragma unroll
    for (int ih = 0; ih < 2; ih++) {
#pragma unroll
        for (int ip = 0; ip < 2; ip++) {
            const int i = ih * 2 + ip;
            const int r0 = row0 + ih * 64 + ty * 4 + 2 * ip;
            float olo[8], ohi[8];
#pragma unroll
            for (int j = 0; j < 8; j++) {
                olo[j] = f2lo(acc[i][j]) * alpha + bb[j];
                ohi[j] = f2hi(acc[i][j]) * alpha + bb[j];
            }
#pragma unroll
            for (int jh = 0; jh < 2; jh++) {
                const int c = col0 + jh * 64 + tx * 4;
                if (HAS_ADD) {
                    float4 x0 = *(const float4*)&Xm[(size_t)r0 * N + c];
                    float4 x1 = *(const float4*)&Xm[(size_t)(r0 + 1) * N + c];
                    olo[jh*4+0] += x0.x; olo[jh*4+1] += x0.y;
                    olo[jh*4+2] += x0.z; olo[jh*4+3] += x0.w;
                    ohi[jh*4+0] += x1.x; ohi[jh*4+1] += x1.y;
                    ohi[jh*4+2] += x1.z; ohi[jh*4+3] += x1.w;
                }
                *(float4*)&C[(size_t)r0 * N + c] =
                    make_float4(olo[jh*4+0], olo[jh*4+1], olo[jh*4+2], olo[jh*4+3]);
                *(float4*)&C[(size_t)(r0 + 1) * N + c] =
                    make_float4(ohi[jh*4+0], ohi[jh*4+1], ohi[jh*4+2], ohi[jh*4+3]);
            }
        }
    }
}

// ---------------- fp32 -> bf16 hi/lo split (Q, K) ----------------
__global__ void split_kernel(const float* __restrict__ s,
                             __nv_bfloat16* __restrict__ h, __nv_bfloat16* __restrict__ l) {
    size_t i = ((size_t)blockIdx.x * 256 + threadIdx.x) * 4;
    float4 v = *(const float4*)(s + i);
    float f[4] = {v.x, v.y, v.z, v.w};
    __nv_bfloat16 hv[4], lv[4];
#pragma unroll
    for (int j = 0; j < 4; j++) {
        hv[j] = __float2bfloat16(f[j]);
        lv[j] = __float2bfloat16(f[j] - __bfloat162float(hv[j]));
    }
    *(uint2*)(h + i) = *(uint2*)hv;
    *(uint2*)(l + i) = *(uint2*)lv;
}

// ---------------- V [BNR,F] fp32 -> V^T [F,BNR] bf16 hi/lo ----------------
__global__ void vt_kernel(const float* __restrict__ V,
                          __nv_bfloat16* __restrict__ th, __nv_bfloat16* __restrict__ tl) {
    __shared__ float t[32][33];
    const int m0 = blockIdx.y * 32, f0 = blockIdx.x * 32;
    const int tx = threadIdx.x, ty = threadIdx.y;   // 32 x 8
#pragma unroll
    for (int i = 0; i < 4; i++)
        t[ty + i * 8][tx] = V[(size_t)(m0 + ty + i * 8) * F_DIM + f0 + tx];
    __syncthreads();
#pragma unroll
    for (int i = 0; i < 4; i++) {
        float v = t[tx][ty + i * 8];
        __nv_bfloat16 h = __float2bfloat16(v);
        __nv_bfloat16 l = __float2bfloat16(v - __bfloat162float(h));
        size_t o = (size_t)(f0 + ty + i * 8) * BNR + m0 + tx;
        th[o] = h; tl[o] = l;
    }
}

// ---------------- 3xBF16 warp-MMA GEMM (HMMA path, compute_103-safe) ----------------
// C[m][n] = alpha * sum_k A[m][k] * B[n][k]   (A, B k-contiguous, hi/lo split)
// block tile 128x128, BK=32, 256 threads (8 warps, 4m x 2n), warp tile 32x64.
// smem per buffer: 4 arrays x 128 rows x 112B (row = 64B data + 48B pad; 16B aligned,
// frag-LDS conflict-free: r*28 mod 32 distinct over 8 rows). Double buffered.
#define MMA_RS     112                       // smem row stride bytes
#define MMA_ARR    (128 * MMA_RS)            // 14336
#define MMA_BUF    (4 * MMA_ARR)             // 57344
#define MMA_SMEM   (2 * MMA_BUF)             // 114688

__global__ void __launch_bounds__(256) mma3_kernel(
    const __nv_bfloat16* __restrict__ Ah, const __nv_bfloat16* __restrict__ Al,
    const __nv_bfloat16* __restrict__ Bh, const __nv_bfloat16* __restrict__ Bl,
    float* __restrict__ C, int K, int ldB, int ldC,
    size_t aBatch, size_t bBatch, size_t cBatch, float alpha)
{
    extern __shared__ __align__(16) char smem[];
    const int tid  = threadIdx.x;
    const int lane = tid & 31, wid = tid >> 5;
    const int wy = wid >> 1, wx = wid & 1;     // warp: rows wy*32.., cols wx*64..
    const int g = lane >> 2, t = lane & 3;

    const size_t aBase = (size_t)blockIdx.z * aBatch + (size_t)(blockIdx.y * 128) * K;
    const size_t bBase = (size_t)blockIdx.z * bBatch + (size_t)(blockIdx.x * 128) * ldB;
    float* Cb = C + (size_t)blockIdx.z * cBatch + (size_t)(blockIdx.y * 128) * ldC
                  + blockIdx.x * 128;

    const uint32_t sb = smem_u32(smem);
    const int lr = tid >> 1;                   // load row 0..127
    const int lc = (tid & 1) * 16;             // elem col 0 / 16

    auto load_buf = [&](int buf, int kc) {
        const size_t ga = aBase + (size_t)lr * K   + kc + lc;
        const size_t gb = bBase + (size_t)lr * ldB + kc + lc;
        const uint32_t so = sb + buf * MMA_BUF + lr * MMA_RS + lc * 2;
        cp16(so,                    Ah + ga); cp16(so + 16,                Ah + ga + 8);
        cp16(so + MMA_ARR,          Al + ga); cp16(so + MMA_ARR + 16,      Al + ga + 8);
        cp16(so + 2 * MMA_ARR,      Bh + gb); cp16(so + 2 * MMA_ARR + 16,  Bh + gb + 8);
        cp16(so + 3 * MMA_ARR,      Bl + gb); cp16(so + 3 * MMA_ARR + 16,  Bl + gb + 8);
        cp_commit();
    };

    float acc[2][8][4];
#pragma unroll
    for (int i = 0; i < 2; i++)
#pragma unroll
        for (int j = 0; j < 8; j++)
#pragma unroll
            for (int q = 0; q < 4; q++) acc[i][j][q] = 0.0f;

    const int nCh = K >> 5;
    load_buf(0, 0);
    for (int c = 0; c < nCh; c++) {
        if (c + 1 < nCh) { load_buf((c + 1) & 1, (c + 1) << 5); cp_wait<1>(); }
        else             { cp_wait<0>(); }
        __syncthreads();
        const uint32_t s0 = sb + (c & 1) * MMA_BUF;
#pragma unroll
        for (int ks = 0; ks < 2; ks++) {
            const uint32_t kb = ks * 32 + t * 4;    // byte offset of k = ks*16 + 2t
            uint32_t ah[2][4], al2[2][4];
#pragma unroll
            for (int mt = 0; mt < 2; mt++) {
                const uint32_t ra = s0 + (wy * 32 + mt * 16 + g) * MMA_RS + kb;
                ah[mt][0]  = lds32(ra);
                ah[mt][1]  = lds32(ra + 8 * MMA_RS);
                ah[mt][2]  = lds32(ra + 16);
                ah[mt][3]  = lds32(ra + 8 * MMA_RS + 16);
                al2[mt][0] = lds32(ra + MMA_ARR);
                al2[mt][1] = lds32(ra + MMA_ARR + 8 * MMA_RS);
                al2[mt][2] = lds32(ra + MMA_ARR + 16);
                al2[mt][3] = lds32(ra + MMA_ARR + 8 * MMA_RS + 16);
            }
            uint32_t bh[8][2], bl[8][2];
#pragma unroll
            for (int nt = 0; nt < 8; nt++) {
                const uint32_t rb = s0 + 2 * MMA_ARR + (wx * 64 + nt * 8 + g) * MMA_RS + kb;
                bh[nt][0] = lds32(rb);
                bh[nt][1] = lds32(rb + 16);
                bl[nt][0] = lds32(rb + MMA_ARR);
                bl[nt][1] = lds32(rb + MMA_ARR + 16);
            }
#pragma unroll
            for (int mt = 0; mt < 2; mt++)
#pragma unroll
                for (int nt = 0; nt < 8; nt++) {
                    mma16816(acc[mt][nt], ah[mt],  bh[nt]);   // hi*hi
                    mma16816(acc[mt][nt], ah[mt],  bl[nt]);   // hi*lo
                    mma16816(acc[mt][nt], al2[mt], bh[nt]);   // lo*hi
                }
        }
        __syncthreads();
    }

    // epilogue: c0,c1 -> (row, col 2t..2t+1); c2,c3 -> (row+8, same cols)
#pragma unroll
    for (int mt = 0; mt < 2; mt++) {
        const int row = wy * 32 + mt * 16 + g;
#pragma unroll
        for (int nt = 0; nt < 8; nt++) {
            const int col = wx * 64 + nt * 8 + 2 * t;
            float2 v0 = make_float2(acc[mt][nt][0] * alpha, acc[mt][nt][1] * alpha);
            float2 v1 = make_float2(acc[mt][nt][2] * alpha, acc[mt][nt][3] * alpha);
            *(float2*)(Cb + (size_t)row * ldC + col)       = v0;
            *(float2*)(Cb + (size_t)(row + 8) * ldC + col) = v1;
        }
    }
}

// ---------------- rowwise softmax + bf16 hi/lo split of P ----------------
__device__ __forceinline__ unsigned pk2(__nv_bfloat16 a, __nv_bfloat16 b) {
    __nv_bfloat162 t2; t2.x = a; t2.y = b;
    return *(unsigned*)&t2;
}
__global__ void softmax_kernel(const float* __restrict__ S,
                               __nv_bfloat16* __restrict__ ph, __nv_bfloat16* __restrict__ pl) {
    __shared__ float red[8];
    const size_t row = blockIdx.x;
    const float4* r = (const float4*)(S + row * (size_t)N_SEQ);
    const int tid = threadIdx.x;        // 256 threads, 8 floats each
    float4 v0 = r[tid * 2], v1 = r[tid * 2 + 1];

    float m = fmaxf(fmaxf(fmaxf(v0.x, v0.y), fmaxf(v0.z, v0.w)),
                    fmaxf(fmaxf(v1.x, v1.y), fmaxf(v1.z, v1.w)));
#pragma unroll
    for (int o = 16; o; o >>= 1) m = fmaxf(m, __shfl_xor_sync(0xffffffffu, m, o));
    if ((tid & 31) == 0) red[tid >> 5] = m;
    __syncthreads();
    float mm = red[0];
#pragma unroll
    for (int i = 1; i < 8; i++) mm = fmaxf(mm, red[i]);
    __syncthreads();

    v0.x = __expf(v0.x - mm); v0.y = __expf(v0.y - mm);
    v0.z = __expf(v0.z - mm); v0.w = __expf(v0.w - mm);
    v1.x = __expf(v1.x - mm); v1.y = __expf(v1.y - mm);
    v1.z = __expf(v1.z - mm); v1.w = __expf(v1.w - mm);

    float s = ((v0.x + v0.y) + (v0.z + v0.w)) + ((v1.x + v1.y) + (v1.z + v1.w));
#pragma unroll
    for (int o = 16; o; o >>= 1) s += __shfl_xor_sync(0xffffffffu, s, o);
    if ((tid & 31) == 0) red[tid >> 5] = s;
    __syncthreads();
    float tot = ((red[0] + red[1]) + (red[2] + red[3])) +
                ((red[4] + red[5]) + (red[6] + red[7]));
    float inv = __frcp_rn(tot);

    float f[8] = {v0.x * inv, v0.y * inv, v0.z * inv, v0.w * inv,
                  v1.x * inv, v1.y * inv, v1.z * inv, v1.w * inv};
    __nv_bfloat16 h[8], l[8];
#pragma unroll
    for (int j = 0; j < 8; j++) {
        h[j] = __float2bfloat16(f[j]);
        l[j] = __float2bfloat16(f[j] - __bfloat162float(h[j]));
    }
    const size_t base = row * (size_t)N_SEQ + tid * 8;
    uint4 H, L;
    H.x = pk2(h[0], h[1]); H.y = pk2(h[2], h[3]);
    H.z = pk2(h[4], h[5]); H.w = pk2(h[6], h[7]);
    L.x = pk2(l[0], l[1]); L.y = pk2(l[2], l[3]);
    L.z = pk2(l[4], l[5]); L.w = pk2(l[6], l[7]);
    *(uint4*)(ph + base) = H;
    *(uint4*)(pl + base) = L;
}

// ---------------- launch ----------------
extern "C" void kernel_launch(void* const* d_in, const int* in_sizes, int n_in,
                              void* d_out, int out_size) {
    const float* x  = (const float*)d_in[0];
    const float* p  = (const float*)d_in[1];
    const float* Wq = (const float*)d_in[2];
    const float* bq = (const float*)d_in[3];
    const float* Wk = (const float*)d_in[4];
    const float* bk = (const float*)d_in[5];
    const float* Wv = (const float*)d_in[6];
    const float* bv = (const float*)d_in[7];
    const float* W1 = (const float*)d_in[8];
    const float* b1 = (const float*)d_in[9];
    const float* W2 = (const float*)d_in[10];
    const float* b2 = (const float*)d_in[11];
    float* out = (float*)d_out;

    float *hbuf, *qbuf, *kbuf, *vbuf, *sbuf;
    __nv_bfloat16 *qhb, *qlb, *khb, *klb, *vthb, *vtlb, *phb, *plb;
    cudaGetSymbolAddress((void**)&hbuf, g_h);
    cudaGetSymbolAddress((void**)&qbuf, g_q);
    cudaGetSymbolAddress((void**)&kbuf, g_k);
    cudaGetSymbolAddress((void**)&vbuf, g_v);
    cudaGetSymbolAddress((void**)&sbuf, g_s);
    cudaGetSymbolAddress((void**)&qhb, g_qh);
    cudaGetSymbolAddress((void**)&qlb, g_ql);
    cudaGetSymbolAddress((void**)&khb, g_kh);
    cudaGetSymbolAddress((void**)&klb, g_kl);
    cudaGetSymbolAddress((void**)&vthb, g_vth);
    cudaGetSymbolAddress((void**)&vtlb, g_vtl);
    cudaGetSymbolAddress((void**)&phb, g_ph);
    cudaGetSymbolAddress((void**)&plb, g_pl);

    cudaFuncSetAttribute(mma3_kernel, cudaFuncAttributeMaxDynamicSharedMemorySize, MMA_SMEM);

    // 1) R = relu(p @ W1^T + b1)   (R temporarily in g_q)
    pos_kernel<<<(BNR * F_DIM) / 256, 256>>>(p, W1, b1, qbuf);

    // 2) H = R @ W2^T + b2 + x
    gemm_kernel<true, true, true><<<dim3(F_DIM / BN, BNR / BM, 1), NT>>>(
        qbuf, W2, hbuf, b2, x, BNR, F_DIM, F_DIM, 0, 0, 0, 1.0f);

    // 3) QKV projections (reference swaps: q uses Wk/bk, k uses Wq/bq)
    gemm_kernel<true, true, false><<<dim3(F_DIM / BN, BNR / BM, 1), NT>>>(
        hbuf, Wk, qbuf, bk, nullptr, BNR, F_DIM, F_DIM, 0, 0, 0, 1.0f);
    gemm_kernel<true, true, false><<<dim3(F_DIM / BN, BNR / BM, 1), NT>>>(
        hbuf, Wq, kbuf, bq, nullptr, BNR, F_DIM, F_DIM, 0, 0, 0, 1.0f);
    gemm_kernel<true, true, false><<<dim3(F_DIM / BN, BNR / BM, 1), NT>>>(
        hbuf, Wv, vbuf, bv, nullptr, BNR, F_DIM, F_DIM, 0, 0, 0, 1.0f);

    // 4) bf16 hi/lo splits for Q, K and V^T
    split_kernel<<<(BNR * F_DIM) / 1024, 256>>>(qbuf, qhb, qlb);
    split_kernel<<<(BNR * F_DIM) / 1024, 256>>>(kbuf, khb, klb);
    vt_kernel<<<dim3(F_DIM / 32, BNR / 32), dim3(32, 8)>>>(vbuf, vthb, vtlb);

    // 5) S = QK^T / 16  (3xBF16 warp-MMA)
    mma3_kernel<<<dim3(16, 16, 16), 256, MMA_SMEM>>>(
        qhb, qlb, khb, klb, sbuf,
        F_DIM, F_DIM, N_SEQ,
        (size_t)N_SEQ * F_DIM, (size_t)N_SEQ * F_DIM, (size_t)N_SEQ * N_SEQ, 0.0625f);

    // 6) softmax + split P to bf16 hi/lo
    softmax_kernel<<<B_SZ * N_SEQ, 256>>>(sbuf, phb, plb);

    // 7) out = P @ V  (3xBF16 warp-MMA; B = V^T rows, ldB = BNR)
    mma3_kernel<<<dim3(F_DIM / 128, 16, 16), 256, MMA_SMEM>>>(
        phb, plb, vthb, vtlb, out,
        N_SEQ, BNR, F_DIM,
        (size_t)N_SEQ * N_SEQ, (size_t)N_SEQ, (size_t)N_SEQ * F_DIM, 1.0f);
}

// round 12
// speedup vs baseline: 1.7556x; 1.1382x over previous
#include <cuda_runtime.h>
#include <cuda_bf16.h>
#include <cstdint>

#define B_SZ   16
#define N_SEQ  2048
#define F_DIM  256
#define BNR    (B_SZ * N_SEQ)   // 32768 rows

// ---------------- device scratch (no runtime allocation allowed) ----------------
__device__ float g_v[(size_t)BNR * F_DIM];                 // V projection (fp32)
__device__ float g_s[(size_t)B_SZ * N_SEQ * N_SEQ];        // 268 MB scores (fp32)
__device__ __nv_bfloat16 g_rh[(size_t)BNR * F_DIM];        // relu(pos) hi/lo
__device__ __nv_bfloat16 g_rl[(size_t)BNR * F_DIM];
__device__ __nv_bfloat16 g_hh[(size_t)BNR * F_DIM];        // H hi/lo
__device__ __nv_bfloat16 g_hl[(size_t)BNR * F_DIM];
__device__ __nv_bfloat16 g_qh[(size_t)BNR * F_DIM];
__device__ __nv_bfloat16 g_ql[(size_t)BNR * F_DIM];
__device__ __nv_bfloat16 g_kh[(size_t)BNR * F_DIM];
__device__ __nv_bfloat16 g_kl[(size_t)BNR * F_DIM];
__device__ __nv_bfloat16 g_vth[(size_t)F_DIM * BNR];       // V^T hi  [F][BNR]
__device__ __nv_bfloat16 g_vtl[(size_t)F_DIM * BNR];       // V^T lo
__device__ __nv_bfloat16 g_ph[(size_t)B_SZ * N_SEQ * N_SEQ];
__device__ __nv_bfloat16 g_pl[(size_t)B_SZ * N_SEQ * N_SEQ];
// weight splits (each 256x256)
__device__ __nv_bfloat16 g_w2h[F_DIM * F_DIM], g_w2l[F_DIM * F_DIM];
__device__ __nv_bfloat16 g_wbh[F_DIM * F_DIM], g_wbl[F_DIM * F_DIM];  // Wk (used for q)
__device__ __nv_bfloat16 g_wch[F_DIM * F_DIM], g_wcl[F_DIM * F_DIM];  // Wq (used for k)
__device__ __nv_bfloat16 g_wdh[F_DIM * F_DIM], g_wdl[F_DIM * F_DIM];  // Wv

// ---------------- warp-MMA helpers (sm_80+ baseline; valid on compute_103) ----
__device__ __forceinline__ uint32_t smem_u32(const void* p) {
    uint32_t a;
    asm("{ .reg .u64 t; cvta.to.shared.u64 t, %1; cvt.u32.u64 %0, t; }" : "=r"(a) : "l"(p));
    return a;
}
__device__ __forceinline__ void cp16(uint32_t s, const void* g) {
    asm volatile("cp.async.cg.shared.global [%0], [%1], 16;" :: "r"(s), "l"(g) : "memory");
}
template<int N> __device__ __forceinline__ void cp_wait() {
    asm volatile("cp.async.wait_group %0;" :: "n"(N) : "memory");
}
__device__ __forceinline__ void cp_commit() {
    asm volatile("cp.async.commit_group;" ::: "memory");
}
__device__ __forceinline__ uint32_t lds32(uint32_t a) {
    uint32_t v;
    asm volatile("ld.shared.b32 %0, [%1];" : "=r"(v) : "r"(a));
    return v;
}
__device__ __forceinline__ void mma16816(float* c, const uint32_t* a, const uint32_t* b) {
    asm volatile(
        "mma.sync.aligned.m16n8k16.row.col.f32.bf16.bf16.f32 "
        "{%0,%1,%2,%3}, {%4,%5,%6,%7}, {%8,%9}, {%0,%1,%2,%3};"
        : "+f"(c[0]), "+f"(c[1]), "+f"(c[2]), "+f"(c[3])
        : "r"(a[0]), "r"(a[1]), "r"(a[2]), "r"(a[3]), "r"(b[0]), "r"(b[1]));
}
__device__ __forceinline__ unsigned pk2(__nv_bfloat16 a, __nv_bfloat16 b) {
    __nv_bfloat162 t2; t2.x = a; t2.y = b;
    return *(unsigned*)&t2;
}
__device__ __forceinline__ void split1(float v, __nv_bfloat16& h, __nv_bfloat16& l) {
    h = __float2bfloat16(v);
    l = __float2bfloat16(v - __bfloat162float(h));
}

// ---------------- positional encoder: R = relu(p @ W1^T + b1) -> bf16 hi/lo ----------
__global__ void pos_split_kernel(const float* __restrict__ p, const float* __restrict__ W1,
                                 const float* __restrict__ b1,
                                 __nv_bfloat16* __restrict__ rh, __nv_bfloat16* __restrict__ rl) {
    const int gid = blockIdx.x * blockDim.x + threadIdx.x;   // BNR*64 threads
    const int i = gid >> 6;
    const int f0 = (gid & 63) * 4;
    const float p0 = __ldg(p + (size_t)i * 3 + 0);
    const float p1 = __ldg(p + (size_t)i * 3 + 1);
    const float p2 = __ldg(p + (size_t)i * 3 + 2);
    __nv_bfloat16 hv[4], lv[4];
#pragma unroll
    for (int j = 0; j < 4; j++) {
        const int f = f0 + j;
        float r = fmaf(p0, __ldg(W1 + f * 3 + 0),
                  fmaf(p1, __ldg(W1 + f * 3 + 1),
                  fmaf(p2, __ldg(W1 + f * 3 + 2), __ldg(b1 + f))));
        r = fmaxf(r, 0.0f);
        split1(r, hv[j], lv[j]);
    }
    const size_t o = (size_t)i * F_DIM + f0;
    *(uint2*)(rh + o) = *(uint2*)hv;
    *(uint2*)(rl + o) = *(uint2*)lv;
}

// ---------------- generic fp32 -> bf16 hi/lo split (weights) ----------------
__global__ void split_kernel(const float* __restrict__ s,
                             __nv_bfloat16* __restrict__ h, __nv_bfloat16* __restrict__ l) {
    size_t i = ((size_t)blockIdx.x * 256 + threadIdx.x) * 4;
    float4 v = *(const float4*)(s + i);
    float f[4] = {v.x, v.y, v.z, v.w};
    __nv_bfloat16 hv[4], lv[4];
#pragma unroll
    for (int j = 0; j < 4; j++) split1(f[j], hv[j], lv[j]);
    *(uint2*)(h + i) = *(uint2*)hv;
    *(uint2*)(l + i) = *(uint2*)lv;
}

// ---------------- V [BNR,F] fp32 -> V^T [F,BNR] bf16 hi/lo ----------------
__global__ void vt_kernel(const float* __restrict__ V,
                          __nv_bfloat16* __restrict__ th, __nv_bfloat16* __restrict__ tl) {
    __shared__ float t[32][33];
    const int m0 = blockIdx.y * 32, f0 = blockIdx.x * 32;
    const int tx = threadIdx.x, ty = threadIdx.y;   // 32 x 8
#pragma unroll
    for (int i = 0; i < 4; i++)
        t[ty + i * 8][tx] = V[(size_t)(m0 + ty + i * 8) * F_DIM + f0 + tx];
    __syncthreads();
#pragma unroll
    for (int i = 0; i < 4; i++) {
        float v = t[tx][ty + i * 8];
        __nv_bfloat16 h, l;
        split1(v, h, l);
        size_t o = (size_t)(f0 + ty + i * 8) * BNR + m0 + tx;
        th[o] = h; tl[o] = l;
    }
}

// ---------------- shared 3xBF16 mainloop config ----------------
// block tile 128x128, BK=32, 256 threads (8 warps, 4m x 2n), warp tile 32x64.
// smem per buffer: 4 arrays x 128 rows x 112B (row = 64B data + 48B pad).
#define MMA_RS     112                       // smem row stride bytes
#define MMA_ARR    (128 * MMA_RS)            // 14336
#define MMA_BUF    (4 * MMA_ARR)             // 57344
#define MMA_SMEM   (2 * MMA_BUF)             // 114688

// mainloop macro body (shared between mma3 / mma3p): accumulates into acc[2][8][4]
#define MMA3_MAINLOOP(KTOT, LDA, LDB, ABASE, BBASE)                                   \
    const uint32_t sb = smem_u32(smem);                                               \
    const int lr = tid >> 1;                                                          \
    const int lc = (tid & 1) * 16;                                                    \
    auto load_buf = [&](int buf, int kc) {                                            \
        const size_t ga = (ABASE) + (size_t)lr * (LDA) + kc + lc;                     \
        const size_t gb = (BBASE) + (size_t)lr * (LDB) + kc + lc;                     \
        const uint32_t so = sb + buf * MMA_BUF + lr * MMA_RS + lc * 2;                \
        cp16(so,                   Ah + ga); cp16(so + 16,               Ah + ga + 8);\
        cp16(so + MMA_ARR,         Al + ga); cp16(so + MMA_ARR + 16,     Al + ga + 8);\
        cp16(so + 2 * MMA_ARR,     Bh + gb); cp16(so + 2 * MMA_ARR + 16, Bh + gb + 8);\
        cp16(so + 3 * MMA_ARR,     Bl + gb); cp16(so + 3 * MMA_ARR + 16, Bl + gb + 8);\
        cp_commit();                                                                  \
    };                                                                                \
    float acc[2][8][4];                                                               \
    _Pragma("unroll") for (int i = 0; i < 2; i++)                                     \
    _Pragma("unroll") for (int j = 0; j < 8; j++)                                     \
    _Pragma("unroll") for (int q = 0; q < 4; q++) acc[i][j][q] = 0.0f;                \
    const int nCh = (KTOT) >> 5;                                                      \
    load_buf(0, 0);                                                                   \
    for (int c = 0; c < nCh; c++) {                                                   \
        if (c + 1 < nCh) { load_buf((c + 1) & 1, (c + 1) << 5); cp_wait<1>(); }       \
        else             { cp_wait<0>(); }                                            \
        __syncthreads();                                                              \
        const uint32_t s0 = sb + (c & 1) * MMA_BUF;                                   \
        _Pragma("unroll")                                                             \
        for (int ks = 0; ks < 2; ks++) {                                              \
            const uint32_t kb = ks * 32 + t * 4;                                      \
            uint32_t ah[2][4], al2[2][4];                                             \
            _Pragma("unroll")                                                         \
            for (int mt = 0; mt < 2; mt++) {                                          \
                const uint32_t ra = s0 + (wy * 32 + mt * 16 + g) * MMA_RS + kb;       \
                ah[mt][0]  = lds32(ra);                                               \
                ah[mt][1]  = lds32(ra + 8 * MMA_RS);                                  \
                ah[mt][2]  = lds32(ra + 16);                                          \
                ah[mt][3]  = lds32(ra + 8 * MMA_RS + 16);                             \
                al2[mt][0] = lds32(ra + MMA_ARR);                                     \
                al2[mt][1] = lds32(ra + MMA_ARR + 8 * MMA_RS);                        \
                al2[mt][2] = lds32(ra + MMA_ARR + 16);                                \
                al2[mt][3] = lds32(ra + MMA_ARR + 8 * MMA_RS + 16);                   \
            }                                                                         \
            uint32_t bh[8][2], bl[8][2];                                              \
            _Pragma("unroll")                                                         \
            for (int nt = 0; nt < 8; nt++) {                                          \
                const uint32_t rb = s0 + 2 * MMA_ARR + (wx * 64 + nt * 8 + g) * MMA_RS + kb; \
                bh[nt][0] = lds32(rb);                                                \
                bh[nt][1] = lds32(rb + 16);                                           \
                bl[nt][0] = lds32(rb + MMA_ARR);                                      \
                bl[nt][1] = lds32(rb + MMA_ARR + 16);                                 \
            }                                                                         \
            _Pragma("unroll")                                                         \
            for (int mt = 0; mt < 2; mt++)                                            \
            _Pragma("unroll")                                                         \
            for (int nt = 0; nt < 8; nt++) {                                          \
                mma16816(acc[mt][nt], ah[mt],  bh[nt]);                               \
                mma16816(acc[mt][nt], ah[mt],  bl[nt]);                               \
                mma16816(acc[mt][nt], al2[mt], bh[nt]);                               \
            }                                                                         \
        }                                                                             \
        __syncthreads();                                                              \
    }

// ---------------- attention 3xBF16 GEMM (fp32 out, alpha) ----------------
__global__ void __launch_bounds__(256) mma3_kernel(
    const __nv_bfloat16* __restrict__ Ah, const __nv_bfloat16* __restrict__ Al,
    const __nv_bfloat16* __restrict__ Bh, const __nv_bfloat16* __restrict__ Bl,
    float* __restrict__ C, int K, int ldB, int ldC,
    size_t aBatch, size_t bBatch, size_t cBatch, float alpha)
{
    extern __shared__ __align__(16) char smem[];
    const int tid  = threadIdx.x;
    const int lane = tid & 31, wid = tid >> 5;
    const int wy = wid >> 1, wx = wid & 1;
    const int g = lane >> 2, t = lane & 3;

    const size_t aBase = (size_t)blockIdx.z * aBatch + (size_t)(blockIdx.y * 128) * K;
    const size_t bBase = (size_t)blockIdx.z * bBatch + (size_t)(blockIdx.x * 128) * ldB;
    float* Cb = C + (size_t)blockIdx.z * cBatch + (size_t)(blockIdx.y * 128) * ldC
                  + blockIdx.x * 128;

    MMA3_MAINLOOP(K, K, ldB, aBase, bBase)

#pragma unroll
    for (int mt = 0; mt < 2; mt++) {
        const int row = wy * 32 + mt * 16 + g;
#pragma unroll
        for (int nt = 0; nt < 8; nt++) {
            const int col = wx * 64 + nt * 8 + 2 * t;
            float2 v0 = make_float2(acc[mt][nt][0] * alpha, acc[mt][nt][1] * alpha);
            float2 v1 = make_float2(acc[mt][nt][2] * alpha, acc[mt][nt][3] * alpha);
            *(float2*)(Cb + (size_t)row * ldC + col)       = v0;
            *(float2*)(Cb + (size_t)(row + 8) * ldC + col) = v1;
        }
    }
}

// ---------------- projection 3xBF16 GEMM: K=256, N=256, bias, opt residual ------
// SPLIT_OUT: write bf16 hi/lo pair; else fp32. A [M,256] hi/lo, B = weight [256,256].
template<bool HAS_ADD, bool SPLIT_OUT>
__global__ void __launch_bounds__(256) mma3p_kernel(
    const __nv_bfloat16* __restrict__ Ah, const __nv_bfloat16* __restrict__ Al,
    const __nv_bfloat16* __restrict__ Bh, const __nv_bfloat16* __restrict__ Bl,
    const float* __restrict__ bias, const float* __restrict__ X,
    float* __restrict__ Cf,
    __nv_bfloat16* __restrict__ Ch, __nv_bfloat16* __restrict__ Cl)
{
    extern __shared__ __align__(16) char smem[];
    const int tid  = threadIdx.x;
    const int lane = tid & 31, wid = tid >> 5;
    const int wy = wid >> 1, wx = wid & 1;
    const int g = lane >> 2, t = lane & 3;

    const int m0 = blockIdx.y * 128;
    const int n0 = blockIdx.x * 128;
    const size_t aBase = (size_t)m0 * F_DIM;
    const size_t bBase = (size_t)n0 * F_DIM;

    MMA3_MAINLOOP(F_DIM, F_DIM, F_DIM, aBase, bBase)

#pragma unroll
    for (int mt = 0; mt < 2; mt++) {
        const int r0 = m0 + wy * 32 + mt * 16 + g;
#pragma unroll
        for (int nt = 0; nt < 8; nt++) {
            const int gc = n0 + wx * 64 + nt * 8 + 2 * t;
            const float b0 = __ldg(bias + gc), b1 = __ldg(bias + gc + 1);
            float v00 = acc[mt][nt][0] + b0, v01 = acc[mt][nt][1] + b1;
            float v10 = acc[mt][nt][2] + b0, v11 = acc[mt][nt][3] + b1;
            if (HAS_ADD) {
                float2 x0 = *(const float2*)(X + (size_t)r0 * F_DIM + gc);
                float2 x1 = *(const float2*)(X + (size_t)(r0 + 8) * F_DIM + gc);
                v00 += x0.x; v01 += x0.y; v10 += x1.x; v11 += x1.y;
            }
            if (SPLIT_OUT) {
                __nv_bfloat16 h00, l00, h01, l01, h10, l10, h11, l11;
                split1(v00, h00, l00); split1(v01, h01, l01);
                split1(v10, h10, l10); split1(v11, h11, l11);
                *(unsigned*)(Ch + (size_t)r0 * F_DIM + gc)       = pk2(h00, h01);
                *(unsigned*)(Cl + (size_t)r0 * F_DIM + gc)       = pk2(l00, l01);
                *(unsigned*)(Ch + (size_t)(r0 + 8) * F_DIM + gc) = pk2(h10, h11);
                *(unsigned*)(Cl + (size_t)(r0 + 8) * F_DIM + gc) = pk2(l10, l11);
            } else {
                *(float2*)(Cf + (size_t)r0 * F_DIM + gc)       = make_float2(v00, v01);
                *(float2*)(Cf + (size_t)(r0 + 8) * F_DIM + gc) = make_float2(v10, v11);
            }
        }
    }
}

// ---------------- rowwise softmax + bf16 hi/lo split of P ----------------
__global__ void softmax_kernel(const float* __restrict__ S,
                               __nv_bfloat16* __restrict__ ph, __nv_bfloat16* __restrict__ pl) {
    __shared__ float red[8];
    const size_t row = blockIdx.x;
    const float4* r = (const float4*)(S + row * (size_t)N_SEQ);
    const int tid = threadIdx.x;        // 256 threads, 8 floats each
    float4 v0 = r[tid * 2], v1 = r[tid * 2 + 1];

    float m = fmaxf(fmaxf(fmaxf(v0.x, v0.y), fmaxf(v0.z, v0.w)),
                    fmaxf(fmaxf(v1.x, v1.y), fmaxf(v1.z, v1.w)));
#pragma unroll
    for (int o = 16; o; o >>= 1) m = fmaxf(m, __shfl_xor_sync(0xffffffffu, m, o));
    if ((tid & 31) == 0) red[tid >> 5] = m;
    __syncthreads();
    float mm = red[0];
#pragma unroll
    for (int i = 1; i < 8; i++) mm = fmaxf(mm, red[i]);
    __syncthreads();

    v0.x = __expf(v0.x - mm); v0.y = __expf(v0.y - mm);
    v0.z = __expf(v0.z - mm); v0.w = __expf(v0.w - mm);
    v1.x = __expf(v1.x - mm); v1.y = __expf(v1.y - mm);
    v1.z = __expf(v1.z - mm); v1.w = __expf(v1.w - mm);

    float s = ((v0.x + v0.y) + (v0.z + v0.w)) + ((v1.x + v1.y) + (v1.z + v1.w));
#pragma unroll
    for (int o = 16; o; o >>= 1) s += __shfl_xor_sync(0xffffffffu, s, o);
    if ((tid & 31) == 0) red[tid >> 5] = s;
    __syncthreads();
    float tot = ((red[0] + red[1]) + (red[2] + red[3])) +
                ((red[4] + red[5]) + (red[6] + red[7]));
    float inv = __frcp_rn(tot);

    float f[8] = {v0.x * inv, v0.y * inv, v0.z * inv, v0.w * inv,
                  v1.x * inv, v1.y * inv, v1.z * inv, v1.w * inv};
    __nv_bfloat16 h[8], l[8];
#pragma unroll
    for (int j = 0; j < 8; j++) split1(f[j], h[j], l[j]);
    const size_t base = row * (size_t)N_SEQ + tid * 8;
    uint4 H, L;
    H.x = pk2(h[0], h[1]); H.y = pk2(h[2], h[3]);
    H.z = pk2(h[4], h[5]); H.w = pk2(h[6], h[7]);
    L.x = pk2(l[0], l[1]); L.y = pk2(l[2], l[3]);
    L.z = pk2(l[4], l[5]); L.w = pk2(l[6], l[7]);
    *(uint4*)(ph + base) = H;
    *(uint4*)(pl + base) = L;
}

// ---------------- launch ----------------
extern "C" void kernel_launch(void* const* d_in, const int* in_sizes, int n_in,
                              void* d_out, int out_size) {
    const float* x  = (const float*)d_in[0];
    const float* p  = (const float*)d_in[1];
    const float* Wq = (const float*)d_in[2];
    const float* bq = (const float*)d_in[3];
    const float* Wk = (const float*)d_in[4];
    const float* bk = (const float*)d_in[5];
    const float* Wv = (const float*)d_in[6];
    const float* bv = (const float*)d_in[7];
    const float* W1 = (const float*)d_in[8];
    const float* b1 = (const float*)d_in[9];
    const float* W2 = (const float*)d_in[10];
    const float* b2 = (const float*)d_in[11];
    float* out = (float*)d_out;

    float *vbuf, *sbuf;
    __nv_bfloat16 *rh, *rl, *hh, *hl, *qh, *ql, *kh, *kl, *vth, *vtl, *ph, *pl;
    __nv_bfloat16 *w2h, *w2l, *wbh, *wbl, *wch, *wcl, *wdh, *wdl;
    cudaGetSymbolAddress((void**)&vbuf, g_v);
    cudaGetSymbolAddress((void**)&sbuf, g_s);
    cudaGetSymbolAddress((void**)&rh, g_rh);   cudaGetSymbolAddress((void**)&rl, g_rl);
    cudaGetSymbolAddress((void**)&hh, g_hh);   cudaGetSymbolAddress((void**)&hl, g_hl);
    cudaGetSymbolAddress((void**)&qh, g_qh);   cudaGetSymbolAddress((void**)&ql, g_ql);
    cudaGetSymbolAddress((void**)&kh, g_kh);   cudaGetSymbolAddress((void**)&kl, g_kl);
    cudaGetSymbolAddress((void**)&vth, g_vth); cudaGetSymbolAddress((void**)&vtl, g_vtl);
    cudaGetSymbolAddress((void**)&ph, g_ph);   cudaGetSymbolAddress((void**)&pl, g_pl);
    cudaGetSymbolAddress((void**)&w2h, g_w2h); cudaGetSymbolAddress((void**)&w2l, g_w2l);
    cudaGetSymbolAddress((void**)&wbh, g_wbh); cudaGetSymbolAddress((void**)&wbl, g_wbl);
    cudaGetSymbolAddress((void**)&wch, g_wch); cudaGetSymbolAddress((void**)&wcl, g_wcl);
    cudaGetSymbolAddress((void**)&wdh, g_wdh); cudaGetSymbolAddress((void**)&wdl, g_wdl);

    cudaFuncSetAttribute(mma3_kernel, cudaFuncAttributeMaxDynamicSharedMemorySize, MMA_SMEM);
    cudaFuncSetAttribute(mma3p_kernel<true, true>,
                         cudaFuncAttributeMaxDynamicSharedMemorySize, MMA_SMEM);
    cudaFuncSetAttribute(mma3p_kernel<false, true>,
                         cudaFuncAttributeMaxDynamicSharedMemorySize, MMA_SMEM);
    cudaFuncSetAttribute(mma3p_kernel<false, false>,
                         cudaFuncAttributeMaxDynamicSharedMemorySize, MMA_SMEM);

    // 1) R = relu(p @ W1^T + b1) -> bf16 hi/lo
    pos_split_kernel<<<(BNR * 64) / 256, 256>>>(p, W1, b1, rh, rl);

    // 1b) weight splits (reference swaps: q-proj uses Wk, k-proj uses Wq)
    split_kernel<<<(F_DIM * F_DIM) / 1024, 256>>>(W2, w2h, w2l);
    split_kernel<<<(F_DIM * F_DIM) / 1024, 256>>>(Wk, wbh, wbl);
    split_kernel<<<(F_DIM * F_DIM) / 1024, 256>>>(Wq, wch, wcl);
    split_kernel<<<(F_DIM * F_DIM) / 1024, 256>>>(Wv, wdh, wdl);

    // 2) H = R @ W2^T + b2 + x  -> hi/lo
    mma3p_kernel<true, true><<<dim3(2, BNR / 128), 256, MMA_SMEM>>>(
        rh, rl, w2h, w2l, b2, x, nullptr, hh, hl);

    // 3) projections from H (all HMMA)
    mma3p_kernel<false, true><<<dim3(2, BNR / 128), 256, MMA_SMEM>>>(
        hh, hl, wbh, wbl, bk, nullptr, nullptr, qh, ql);        // q = H@Wk^T+bk
    mma3p_kernel<false, true><<<dim3(2, BNR / 128), 256, MMA_SMEM>>>(
        hh, hl, wch, wcl, bq, nullptr, nullptr, kh, kl);        // k = H@Wq^T+bq
    mma3p_kernel<false, false><<<dim3(2, BNR / 128), 256, MMA_SMEM>>>(
        hh, hl, wdh, wdl, bv, nullptr, vbuf, nullptr, nullptr); // v fp32

    // 4) V^T hi/lo
    vt_kernel<<<dim3(F_DIM / 32, BNR / 32), dim3(32, 8)>>>(vbuf, vth, vtl);

    // 5) S = QK^T / 16  (3xBF16 warp-MMA)
    mma3_kernel<<<dim3(16, 16, 16), 256, MMA_SMEM>>>(
        qh, ql, kh, kl, sbuf,
        F_DIM, F_DIM, N_SEQ,
        (size_t)N_SEQ * F_DIM, (size_t)N_SEQ * F_DIM, (size_t)N_SEQ * N_SEQ, 0.0625f);

    // 6) softmax + split P to bf16 hi/lo
    softmax_kernel<<<B_SZ * N_SEQ, 256>>>(sbuf, ph, pl);

    // 7) out = P @ V  (3xBF16 warp-MMA; B = V^T rows, ldB = BNR)
    mma3_kernel<<<dim3(F_DIM / 128, 16, 16), 256, MMA_SMEM>>>(
        ph, pl, vth, vtl, out,
        N_SEQ, BNR, F_DIM,
        (size_t)N_SEQ * N_SEQ, (size_t)N_SEQ, (size_t)N_SEQ * F_DIM, 1.0f);
}

// round 13
// speedup vs baseline: 1.9316x; 1.1003x over previous
#include <cuda_runtime.h>
#include <cuda_bf16.h>
#include <cstdint>

#define B_SZ   16
#define N_SEQ  2048
#define F_DIM  256
#define BNR    (B_SZ * N_SEQ)   // 32768 rows

// ---------------- device scratch (no runtime allocation allowed) ----------------
__device__ float g_v[(size_t)BNR * F_DIM];                 // V projection (fp32)
__device__ float g_s[(size_t)B_SZ * N_SEQ * N_SEQ];        // 268 MB scores (fp32)
__device__ __nv_bfloat16 g_rh[(size_t)BNR * F_DIM];        // relu(pos) hi/lo
__device__ __nv_bfloat16 g_rl[(size_t)BNR * F_DIM];
__device__ __nv_bfloat16 g_hh[(size_t)BNR * F_DIM];        // H hi/lo
__device__ __nv_bfloat16 g_hl[(size_t)BNR * F_DIM];
__device__ __nv_bfloat16 g_qh[(size_t)BNR * F_DIM];
__device__ __nv_bfloat16 g_ql[(size_t)BNR * F_DIM];
__device__ __nv_bfloat16 g_kh[(size_t)BNR * F_DIM];
__device__ __nv_bfloat16 g_kl[(size_t)BNR * F_DIM];
__device__ __nv_bfloat16 g_vth[(size_t)F_DIM * BNR];       // V^T hi  [F][BNR]
__device__ __nv_bfloat16 g_vtl[(size_t)F_DIM * BNR];       // V^T lo
__device__ __nv_bfloat16 g_ph[(size_t)B_SZ * N_SEQ * N_SEQ];
__device__ __nv_bfloat16 g_pl[(size_t)B_SZ * N_SEQ * N_SEQ];
// weight splits (each 256x256)
__device__ __nv_bfloat16 g_w2h[F_DIM * F_DIM], g_w2l[F_DIM * F_DIM];
__device__ __nv_bfloat16 g_wbh[F_DIM * F_DIM], g_wbl[F_DIM * F_DIM];  // Wk (used for q)
__device__ __nv_bfloat16 g_wch[F_DIM * F_DIM], g_wcl[F_DIM * F_DIM];  // Wq (used for k)
__device__ __nv_bfloat16 g_wdh[F_DIM * F_DIM], g_wdl[F_DIM * F_DIM];  // Wv

// ---------------- warp-MMA helpers (sm_80+ baseline; valid on compute_103) ----
__device__ __forceinline__ uint32_t smem_u32(const void* p) {
    uint32_t a;
    asm("{ .reg .u64 t; cvta.to.shared.u64 t, %1; cvt.u32.u64 %0, t; }" : "=r"(a) : "l"(p));
    return a;
}
__device__ __forceinline__ void cp16(uint32_t s, const void* g) {
    asm volatile("cp.async.cg.shared.global [%0], [%1], 16;" :: "r"(s), "l"(g) : "memory");
}
template<int N> __device__ __forceinline__ void cp_wait() {
    asm volatile("cp.async.wait_group %0;" :: "n"(N) : "memory");
}
__device__ __forceinline__ void cp_commit() {
    asm volatile("cp.async.commit_group;" ::: "memory");
}
__device__ __forceinline__ uint32_t lds32(uint32_t a) {
    uint32_t v;
    asm volatile("ld.shared.b32 %0, [%1];" : "=r"(v) : "r"(a));
    return v;
}
__device__ __forceinline__ void mma16816(float* c, const uint32_t* a, const uint32_t* b) {
    asm volatile(
        "mma.sync.aligned.m16n8k16.row.col.f32.bf16.bf16.f32 "
        "{%0,%1,%2,%3}, {%4,%5,%6,%7}, {%8,%9}, {%0,%1,%2,%3};"
        : "+f"(c[0]), "+f"(c[1]), "+f"(c[2]), "+f"(c[3])
        : "r"(a[0]), "r"(a[1]), "r"(a[2]), "r"(a[3]), "r"(b[0]), "r"(b[1]));
}
__device__ __forceinline__ unsigned pk2(__nv_bfloat16 a, __nv_bfloat16 b) {
    __nv_bfloat162 t2; t2.x = a; t2.y = b;
    return *(unsigned*)&t2;
}
__device__ __forceinline__ void split1(float v, __nv_bfloat16& h, __nv_bfloat16& l) {
    h = __float2bfloat16(v);
    l = __float2bfloat16(v - __bfloat162float(h));
}

// ---------------- positional encoder: R = relu(p @ W1^T + b1) -> bf16 hi/lo ----------
__global__ void pos_split_kernel(const float* __restrict__ p, const float* __restrict__ W1,
                                 const float* __restrict__ b1,
                                 __nv_bfloat16* __restrict__ rh, __nv_bfloat16* __restrict__ rl) {
    const int gid = blockIdx.x * blockDim.x + threadIdx.x;   // BNR*64 threads
    const int i = gid >> 6;
    const int f0 = (gid & 63) * 4;
    const float p0 = __ldg(p + (size_t)i * 3 + 0);
    const float p1 = __ldg(p + (size_t)i * 3 + 1);
    const float p2 = __ldg(p + (size_t)i * 3 + 2);
    __nv_bfloat16 hv[4], lv[4];
#pragma unroll
    for (int j = 0; j < 4; j++) {
        const int f = f0 + j;
        float r = fmaf(p0, __ldg(W1 + f * 3 + 0),
                  fmaf(p1, __ldg(W1 + f * 3 + 1),
                  fmaf(p2, __ldg(W1 + f * 3 + 2), __ldg(b1 + f))));
        r = fmaxf(r, 0.0f);
        split1(r, hv[j], lv[j]);
    }
    const size_t o = (size_t)i * F_DIM + f0;
    *(uint2*)(rh + o) = *(uint2*)hv;
    *(uint2*)(rl + o) = *(uint2*)lv;
}

// ---------------- 4 weights fp32 -> bf16 hi/lo split, one launch ----------------
__global__ void split4_kernel(const float* __restrict__ s0, const float* __restrict__ s1,
                              const float* __restrict__ s2, const float* __restrict__ s3,
                              __nv_bfloat16* __restrict__ h0, __nv_bfloat16* __restrict__ l0,
                              __nv_bfloat16* __restrict__ h1, __nv_bfloat16* __restrict__ l1,
                              __nv_bfloat16* __restrict__ h2, __nv_bfloat16* __restrict__ l2,
                              __nv_bfloat16* __restrict__ h3, __nv_bfloat16* __restrict__ l3) {
    const float* s; __nv_bfloat16 *h, *l;
    switch (blockIdx.y) {
        case 0:  s = s0; h = h0; l = l0; break;
        case 1:  s = s1; h = h1; l = l1; break;
        case 2:  s = s2; h = h2; l = l2; break;
        default: s = s3; h = h3; l = l3; break;
    }
    size_t i = ((size_t)blockIdx.x * 256 + threadIdx.x) * 4;
    float4 v = *(const float4*)(s + i);
    float f[4] = {v.x, v.y, v.z, v.w};
    __nv_bfloat16 hv[4], lv[4];
#pragma unroll
    for (int j = 0; j < 4; j++) split1(f[j], hv[j], lv[j]);
    *(uint2*)(h + i) = *(uint2*)hv;
    *(uint2*)(l + i) = *(uint2*)lv;
}

// ---------------- V [BNR,F] fp32 -> V^T [F,BNR] bf16 hi/lo ----------------
__global__ void vt_kernel(const float* __restrict__ V,
                          __nv_bfloat16* __restrict__ th, __nv_bfloat16* __restrict__ tl) {
    __shared__ float t[32][33];
    const int m0 = blockIdx.y * 32, f0 = blockIdx.x * 32;
    const int tx = threadIdx.x, ty = threadIdx.y;   // 32 x 8
#pragma unroll
    for (int i = 0; i < 4; i++)
        t[ty + i * 8][tx] = V[(size_t)(m0 + ty + i * 8) * F_DIM + f0 + tx];
    __syncthreads();
#pragma unroll
    for (int i = 0; i < 4; i++) {
        float v = t[tx][ty + i * 8];
        __nv_bfloat16 h, l;
        split1(v, h, l);
        size_t o = (size_t)(f0 + ty + i * 8) * BNR + m0 + tx;
        th[o] = h; tl[o] = l;
    }
}

// ---------------- shared 3xBF16 mainloop config ----------------
// block tile 128x128, BK=32, 256 threads (8 warps, 4m x 2n), warp tile 32x64.
// smem row stride 80B (64B data + 16B pad): stride=20 words; g*20 mod 32 =
// {0,20,8,28,16,4,24,12} distinct, +t(0..3) covers all 32 banks -> conflict-free
// fragment loads. 2 buffers x 4 arrays x 128 x 80B = 80 KB -> 2 CTAs/SM.
#define MMA_RS     80                        // smem row stride bytes
#define MMA_ARR    (128 * MMA_RS)            // 10240
#define MMA_BUF    (4 * MMA_ARR)             // 40960
#define MMA_SMEM   (2 * MMA_BUF)             // 81920

// mainloop macro body (shared between mma3 / mma3p): accumulates into acc[2][8][4].
// B-fragments loaded per-nt to keep live registers ~100 (2 CTA/SM at 128-reg cap).
#define MMA3_MAINLOOP(KTOT, LDA, LDB, ABASE, BBASE)                                   \
    const uint32_t sb = smem_u32(smem);                                               \
    const int lr = tid >> 1;                                                          \
    const int lc = (tid & 1) * 16;                                                    \
    auto load_buf = [&](int buf, int kc) {                                            \
        const size_t ga = (ABASE) + (size_t)lr * (LDA) + kc + lc;                     \
        const size_t gb = (BBASE) + (size_t)lr * (LDB) + kc + lc;                     \
        const uint32_t so = sb + buf * MMA_BUF + lr * MMA_RS + lc * 2;                \
        cp16(so,                   Ah + ga); cp16(so + 16,               Ah + ga + 8);\
        cp16(so + MMA_ARR,         Al + ga); cp16(so + MMA_ARR + 16,     Al + ga + 8);\
        cp16(so + 2 * MMA_ARR,     Bh + gb); cp16(so + 2 * MMA_ARR + 16, Bh + gb + 8);\
        cp16(so + 3 * MMA_ARR,     Bl + gb); cp16(so + 3 * MMA_ARR + 16, Bl + gb + 8);\
        cp_commit();                                                                  \
    };                                                                                \
    float acc[2][8][4];                                                               \
    _Pragma("unroll") for (int i = 0; i < 2; i++)                                     \
    _Pragma("unroll") for (int j = 0; j < 8; j++)                                     \
    _Pragma("unroll") for (int q = 0; q < 4; q++) acc[i][j][q] = 0.0f;                \
    const int nCh = (KTOT) >> 5;                                                      \
    load_buf(0, 0);                                                                   \
    for (int c = 0; c < nCh; c++) {                                                   \
        if (c + 1 < nCh) { load_buf((c + 1) & 1, (c + 1) << 5); cp_wait<1>(); }       \
        else             { cp_wait<0>(); }                                            \
        __syncthreads();                                                              \
        const uint32_t s0 = sb + (c & 1) * MMA_BUF;                                   \
        _Pragma("unroll")                                                             \
        for (int ks = 0; ks < 2; ks++) {                                              \
            const uint32_t kb = ks * 32 + t * 4;                                      \
            uint32_t ah[2][4], al2[2][4];                                             \
            _Pragma("unroll")                                                         \
            for (int mt = 0; mt < 2; mt++) {                                          \
                const uint32_t ra = s0 + (wy * 32 + mt * 16 + g) * MMA_RS + kb;       \
                ah[mt][0]  = lds32(ra);                                               \
                ah[mt][1]  = lds32(ra + 8 * MMA_RS);                                  \
                ah[mt][2]  = lds32(ra + 16);                                          \
                ah[mt][3]  = lds32(ra + 8 * MMA_RS + 16);                             \
                al2[mt][0] = lds32(ra + MMA_ARR);                                     \
                al2[mt][1] = lds32(ra + MMA_ARR + 8 * MMA_RS);                        \
                al2[mt][2] = lds32(ra + MMA_ARR + 16);                                \
                al2[mt][3] = lds32(ra + MMA_ARR + 8 * MMA_RS + 16);                   \
            }                                                                         \
            _Pragma("unroll")                                                         \
            for (int nt = 0; nt < 8; nt++) {                                          \
                const uint32_t rb = s0 + 2 * MMA_ARR + (wx * 64 + nt * 8 + g) * MMA_RS + kb; \
                uint32_t bh[2], bl[2];                                                \
                bh[0] = lds32(rb);           bh[1] = lds32(rb + 16);                  \
                bl[0] = lds32(rb + MMA_ARR); bl[1] = lds32(rb + MMA_ARR + 16);        \
                mma16816(acc[0][nt], ah[0],  bh);                                     \
                mma16816(acc[1][nt], ah[1],  bh);                                     \
                mma16816(acc[0][nt], ah[0],  bl);                                     \
                mma16816(acc[1][nt], ah[1],  bl);                                     \
                mma16816(acc[0][nt], al2[0], bh);                                     \
                mma16816(acc[1][nt], al2[1], bh);                                     \
            }                                                                         \
        }                                                                             \
        __syncthreads();                                                              \
    }

// ---------------- attention 3xBF16 GEMM (fp32 out, alpha) ----------------
__global__ void __launch_bounds__(256, 2) mma3_kernel(
    const __nv_bfloat16* __restrict__ Ah, const __nv_bfloat16* __restrict__ Al,
    const __nv_bfloat16* __restrict__ Bh, const __nv_bfloat16* __restrict__ Bl,
    float* __restrict__ C, int K, int ldB, int ldC,
    size_t aBatch, size_t bBatch, size_t cBatch, float alpha)
{
    extern __shared__ __align__(16) char smem[];
    const int tid  = threadIdx.x;
    const int lane = tid & 31, wid = tid >> 5;
    const int wy = wid >> 1, wx = wid & 1;
    const int g = lane >> 2, t = lane & 3;

    const size_t aBase = (size_t)blockIdx.z * aBatch + (size_t)(blockIdx.y * 128) * K;
    const size_t bBase = (size_t)blockIdx.z * bBatch + (size_t)(blockIdx.x * 128) * ldB;
    float* Cb = C + (size_t)blockIdx.z * cBatch + (size_t)(blockIdx.y * 128) * ldC
                  + blockIdx.x * 128;

    MMA3_MAINLOOP(K, K, ldB, aBase, bBase)

#pragma unroll
    for (int mt = 0; mt < 2; mt++) {
        const int row = wy * 32 + mt * 16 + g;
#pragma unroll
        for (int nt = 0; nt < 8; nt++) {
            const int col = wx * 64 + nt * 8 + 2 * t;
            float2 v0 = make_float2(acc[mt][nt][0] * alpha, acc[mt][nt][1] * alpha);
            float2 v1 = make_float2(acc[mt][nt][2] * alpha, acc[mt][nt][3] * alpha);
            *(float2*)(Cb + (size_t)row * ldC + col)       = v0;
            *(float2*)(Cb + (size_t)(row + 8) * ldC + col) = v1;
        }
    }
}

// ---------------- projection 3xBF16 GEMM: K=256, N=256, bias, opt residual ------
// SPLIT_OUT: write bf16 hi/lo pair; else fp32. A [M,256] hi/lo, B = weight [256,256].
template<bool HAS_ADD, bool SPLIT_OUT>
__global__ void __launch_bounds__(256, 2) mma3p_kernel(
    const __nv_bfloat16* __restrict__ Ah, const __nv_bfloat16* __restrict__ Al,
    const __nv_bfloat16* __restrict__ Bh, const __nv_bfloat16* __restrict__ Bl,
    const float* __restrict__ bias, const float* __restrict__ X,
    float* __restrict__ Cf,
    __nv_bfloat16* __restrict__ Ch, __nv_bfloat16* __restrict__ Cl)
{
    extern __shared__ __align__(16) char smem[];
    const int tid  = threadIdx.x;
    const int lane = tid & 31, wid = tid >> 5;
    const int wy = wid >> 1, wx = wid & 1;
    const int g = lane >> 2, t = lane & 3;

    const int m0 = blockIdx.y * 128;
    const int n0 = blockIdx.x * 128;
    const size_t aBase = (size_t)m0 * F_DIM;
    const size_t bBase = (size_t)n0 * F_DIM;

    MMA3_MAINLOOP(F_DIM, F_DIM, F_DIM, aBase, bBase)

#pragma unroll
    for (int mt = 0; mt < 2; mt++) {
        const int r0 = m0 + wy * 32 + mt * 16 + g;
#pragma unroll
        for (int nt = 0; nt < 8; nt++) {
            const int gc = n0 + wx * 64 + nt * 8 + 2 * t;
            const float b0 = __ldg(bias + gc), b1 = __ldg(bias + gc + 1);
            float v00 = acc[mt][nt][0] + b0, v01 = acc[mt][nt][1] + b1;
            float v10 = acc[mt][nt][2] + b0, v11 = acc[mt][nt][3] + b1;
            if (HAS_ADD) {
                float2 x0 = *(const float2*)(X + (size_t)r0 * F_DIM + gc);
                float2 x1 = *(const float2*)(X + (size_t)(r0 + 8) * F_DIM + gc);
                v00 += x0.x; v01 += x0.y; v10 += x1.x; v11 += x1.y;
            }
            if (SPLIT_OUT) {
                __nv_bfloat16 h00, l00, h01, l01, h10, l10, h11, l11;
                split1(v00, h00, l00); split1(v01, h01, l01);
                split1(v10, h10, l10); split1(v11, h11, l11);
                *(unsigned*)(Ch + (size_t)r0 * F_DIM + gc)       = pk2(h00, h01);
                *(unsigned*)(Cl + (size_t)r0 * F_DIM + gc)       = pk2(l00, l01);
                *(unsigned*)(Ch + (size_t)(r0 + 8) * F_DIM + gc) = pk2(h10, h11);
                *(unsigned*)(Cl + (size_t)(r0 + 8) * F_DIM + gc) = pk2(l10, l11);
            } else {
                *(float2*)(Cf + (size_t)r0 * F_DIM + gc)       = make_float2(v00, v01);
                *(float2*)(Cf + (size_t)(r0 + 8) * F_DIM + gc) = make_float2(v10, v11);
            }
        }
    }
}

// ---------------- rowwise softmax + bf16 hi/lo split of P ----------------
__global__ void softmax_kernel(const float* __restrict__ S,
                               __nv_bfloat16* __restrict__ ph, __nv_bfloat16* __restrict__ pl) {
    __shared__ float red[8];
    const size_t row = blockIdx.x;
    const float4* r = (const float4*)(S + row * (size_t)N_SEQ);
    const int tid = threadIdx.x;        // 256 threads, 8 floats each
    float4 v0 = r[tid * 2], v1 = r[tid * 2 + 1];

    float m = fmaxf(fmaxf(fmaxf(v0.x, v0.y), fmaxf(v0.z, v0.w)),
                    fmaxf(fmaxf(v1.x, v1.y), fmaxf(v1.z, v1.w)));
#pragma unroll
    for (int o = 16; o; o >>= 1) m = fmaxf(m, __shfl_xor_sync(0xffffffffu, m, o));
    if ((tid & 31) == 0) red[tid >> 5] = m;
    __syncthreads();
    float mm = red[0];
#pragma unroll
    for (int i = 1; i < 8; i++) mm = fmaxf(mm, red[i]);
    __syncthreads();

    v0.x = __expf(v0.x - mm); v0.y = __expf(v0.y - mm);
    v0.z = __expf(v0.z - mm); v0.w = __expf(v0.w - mm);
    v1.x = __expf(v1.x - mm); v1.y = __expf(v1.y - mm);
    v1.z = __expf(v1.z - mm); v1.w = __expf(v1.w - mm);

    float s = ((v0.x + v0.y) + (v0.z + v0.w)) + ((v1.x + v1.y) + (v1.z + v1.w));
#pragma unroll
    for (int o = 16; o; o >>= 1) s += __shfl_xor_sync(0xffffffffu, s, o);
    if ((tid & 31) == 0) red[tid >> 5] = s;
    __syncthreads();
    float tot = ((red[0] + red[1]) + (red[2] + red[3])) +
                ((red[4] + red[5]) + (red[6] + red[7]));
    float inv = __frcp_rn(tot);

    float f[8] = {v0.x * inv, v0.y * inv, v0.z * inv, v0.w * inv,
                  v1.x * inv, v1.y * inv, v1.z * inv, v1.w * inv};
    __nv_bfloat16 h[8], l[8];
#pragma unroll
    for (int j = 0; j < 8; j++) split1(f[j], h[j], l[j]);
    const size_t base = row * (size_t)N_SEQ + tid * 8;
    uint4 H, L;
    H.x = pk2(h[0], h[1]); H.y = pk2(h[2], h[3]);
    H.z = pk2(h[4], h[5]); H.w = pk2(h[6], h[7]);
    L.x = pk2(l[0], l[1]); L.y = pk2(l[2], l[3]);
    L.z = pk2(l[4], l[5]); L.w = pk2(l[6], l[7]);
    *(uint4*)(ph + base) = H;
    *(uint4*)(pl + base) = L;
}

// ---------------- launch ----------------
extern "C" void kernel_launch(void* const* d_in, const int* in_sizes, int n_in,
                              void* d_out, int out_size) {
    const float* x  = (const float*)d_in[0];
    const float* p  = (const float*)d_in[1];
    const float* Wq = (const float*)d_in[2];
    const float* bq = (const float*)d_in[3];
    const float* Wk = (const float*)d_in[4];
    const float* bk = (const float*)d_in[5];
    const float* Wv = (const float*)d_in[6];
    const float* bv = (const float*)d_in[7];
    const float* W1 = (const float*)d_in[8];
    const float* b1 = (const float*)d_in[9];
    const float* W2 = (const float*)d_in[10];
    const float* b2 = (const float*)d_in[11];
    float* out = (float*)d_out;

    float *vbuf, *sbuf;
    __nv_bfloat16 *rh, *rl, *hh, *hl, *qh, *ql, *kh, *kl, *vth, *vtl, *ph, *pl;
    __nv_bfloat16 *w2h, *w2l, *wbh, *wbl, *wch, *wcl, *wdh, *wdl;
    cudaGetSymbolAddress((void**)&vbuf, g_v);
    cudaGetSymbolAddress((void**)&sbuf, g_s);
    cudaGetSymbolAddress((void**)&rh, g_rh);   cudaGetSymbolAddress((void**)&rl, g_rl);
    cudaGetSymbolAddress((void**)&hh, g_hh);   cudaGetSymbolAddress((void**)&hl, g_hl);
    cudaGetSymbolAddress((void**)&qh, g_qh);   cudaGetSymbolAddress((void**)&ql, g_ql);
    cudaGetSymbolAddress((void**)&kh, g_kh);   cudaGetSymbolAddress((void**)&kl, g_kl);
    cudaGetSymbolAddress((void**)&vth, g_vth); cudaGetSymbolAddress((void**)&vtl, g_vtl);
    cudaGetSymbolAddress((void**)&ph, g_ph);   cudaGetSymbolAddress((void**)&pl, g_pl);
    cudaGetSymbolAddress((void**)&w2h, g_w2h); cudaGetSymbolAddress((void**)&w2l, g_w2l);
    cudaGetSymbolAddress((void**)&wbh, g_wbh); cudaGetSymbolAddress((void**)&wbl, g_wbl);
    cudaGetSymbolAddress((void**)&wch, g_wch); cudaGetSymbolAddress((void**)&wcl, g_wcl);
    cudaGetSymbolAddress((void**)&wdh, g_wdh); cudaGetSymbolAddress((void**)&wdl, g_wdl);

    cudaFuncSetAttribute(mma3_kernel, cudaFuncAttributeMaxDynamicSharedMemorySize, MMA_SMEM);
    cudaFuncSetAttribute(mma3p_kernel<true, true>,
                         cudaFuncAttributeMaxDynamicSharedMemorySize, MMA_SMEM);
    cudaFuncSetAttribute(mma3p_kernel<false, true>,
                         cudaFuncAttributeMaxDynamicSharedMemorySize, MMA_SMEM);
    cudaFuncSetAttribute(mma3p_kernel<false, false>,
                         cudaFuncAttributeMaxDynamicSharedMemorySize, MMA_SMEM);

    // 1) R = relu(p @ W1^T + b1) -> bf16 hi/lo
    pos_split_kernel<<<(BNR * 64) / 256, 256>>>(p, W1, b1, rh, rl);

    // 1b) weight splits in one launch (reference swaps: q-proj uses Wk, k-proj uses Wq)
    split4_kernel<<<dim3((F_DIM * F_DIM) / 1024, 4), 256>>>(
        W2, Wk, Wq, Wv, w2h, w2l, wbh, wbl, wch, wcl, wdh, wdl);

    // 2) H = R @ W2^T + b2 + x  -> hi/lo
    mma3p_kernel<true, true><<<dim3(2, BNR / 128), 256, MMA_SMEM>>>(
        rh, rl, w2h, w2l, b2, x, nullptr, hh, hl);

    // 3) projections from H (all HMMA)
    mma3p_kernel<false, true><<<dim3(2, BNR / 128), 256, MMA_SMEM>>>(
        hh, hl, wbh, wbl, bk, nullptr, nullptr, qh, ql);        // q = H@Wk^T+bk
    mma3p_kernel<false, true><<<dim3(2, BNR / 128), 256, MMA_SMEM>>>(
        hh, hl, wch, wcl, bq, nullptr, nullptr, kh, kl);        // k = H@Wq^T+bq
    mma3p_kernel<false, false><<<dim3(2, BNR / 128), 256, MMA_SMEM>>>(
        hh, hl, wdh, wdl, bv, nullptr, vbuf, nullptr, nullptr); // v fp32

    // 4) V^T hi/lo
    vt_kernel<<<dim3(F_DIM / 32, BNR / 32), dim3(32, 8)>>>(vbuf, vth, vtl);

    // 5) S = QK^T / 16  (3xBF16 warp-MMA)
    mma3_kernel<<<dim3(16, 16, 16), 256, MMA_SMEM>>>(
        qh, ql, kh, kl, sbuf,
        F_DIM, F_DIM, N_SEQ,
        (size_t)N_SEQ * F_DIM, (size_t)N_SEQ * F_DIM, (size_t)N_SEQ * N_SEQ, 0.0625f);

    // 6) softmax + split P to bf16 hi/lo
    softmax_kernel<<<B_SZ * N_SEQ, 256>>>(sbuf, ph, pl);

    // 7) out = P @ V  (3xBF16 warp-MMA; B = V^T rows, ldB = BNR)
    mma3_kernel<<<dim3(F_DIM / 128, 16, 16), 256, MMA_SMEM>>>(
        ph, pl, vth, vtl, out,
        N_SEQ, BNR, F_DIM,
        (size_t)N_SEQ * N_SEQ, (size_t)N_SEQ, (size_t)N_SEQ * F_DIM, 1.0f);
}